// round 1
// baseline (speedup 1.0000x reference)
#include <cuda_runtime.h>
#include <math.h>

// ---------------- problem constants ----------------
constexpr int NU = 50000, NF = 50000, NN = 100000;
constexpr int D  = 64,    H2 = 32,    FU = 256;
constexpr int E  = 500000, EP = 500000, EN = 500000;
constexpr int NH = 4;
constexpr float THRESH = 0.3f;

// ---------------- device scratch (no allocs allowed) ----------------
__device__ float g_u[NU * D];
__device__ float g_f[NF * D];
__device__ float g_x[NN * D];      // conv ping
__device__ float g_y[NN * D];      // conv pong
__device__ float g_aggP[NN * D];
__device__ float g_aggN[NN * D];
__device__ float g_cntP[NN];       // becomes 1/max(cnt,1)
__device__ float g_cntN[NN];
__device__ float g_maskF[E];
__device__ float g_maskS[E];
__device__ float g_we[E];
__device__ float g_norm[E];
__device__ float g_deg[NN];        // becomes dis
__device__ float g_xk[NN * D];
__device__ float g_xk2[NN * D];
__device__ float g_acc[NN * D];
__device__ float g_sums[2];

// ---------------- kernels ----------------

// out[row, c] = relu(dot(feat[row,:256], W[:,c]) + b[c]); 4 rows x 64 cols per block
__global__ void gemm_relu(const float* __restrict__ feat, const float* __restrict__ W,
                          const float* __restrict__ b, float* __restrict__ out, int rows) {
    __shared__ float sfeat[4][FU];
    int row0 = blockIdx.x * 4;
    for (int rr = 0; rr < 4; rr++) {
        int row = row0 + rr;
        if (row < rows)
            for (int k = threadIdx.x; k < FU; k += 256)
                sfeat[rr][k] = feat[row * FU + k];
    }
    __syncthreads();
    int c = threadIdx.x & 63;
    int r = threadIdx.x >> 6;
    int row = row0 + r;
    if (row >= rows) return;
    float acc = b[c];
#pragma unroll 8
    for (int k = 0; k < FU; k++)
        acc += sfeat[r][k] * W[k * D + c];
    out[row * D + c] = fmaxf(acc, 0.f);
}

// per-edge multi-head cosine similarity -> mask_feature
__global__ void sim_kernel(const int* __restrict__ e0, const int* __restrict__ e1,
                           const float* __restrict__ mw) {
    __shared__ float smw[NH * D];
    if (threadIdx.x < NH * D) smw[threadIdx.x] = mw[threadIdx.x];
    __syncthreads();
    int warp = (blockIdx.x * blockDim.x + threadIdx.x) >> 5;
    int lane = threadIdx.x & 31;
    if (warp >= E) return;
    int a = e0[warp], bn = e1[warp];
    float u0 = g_u[a * D + lane],  u1 = g_u[a * D + 32 + lane];
    float f0 = g_f[bn * D + lane], f1 = g_f[bn * D + 32 + lane];
    float sim = 0.f;
#pragma unroll
    for (int h = 0; h < NH; h++) {
        float w0 = smw[h * D + lane], w1 = smw[h * D + 32 + lane];
        float a0 = u0 * w0, a1 = u1 * w1, b0 = f0 * w0, b1 = f1 * w1;
        float ab = a0 * b0 + a1 * b1;
        float aa = a0 * a0 + a1 * a1;
        float bb = b0 * b0 + b1 * b1;
#pragma unroll
        for (int off = 16; off; off >>= 1) {
            ab += __shfl_xor_sync(0xffffffffu, ab, off);
            aa += __shfl_xor_sync(0xffffffffu, aa, off);
            bb += __shfl_xor_sync(0xffffffffu, bb, off);
        }
        sim += ab / (fmaxf(sqrtf(aa), 1e-8f) * fmaxf(sqrtf(bb), 1e-8f));
    }
    if (lane == 0) {
        sim *= (1.f / NH);
        g_maskF[warp] = (sim < THRESH) ? 0.f : sim;
    }
}

__global__ void count_kernel(const int* __restrict__ dst, int n, float* __restrict__ cnt) {
    int i = blockIdx.x * blockDim.x + threadIdx.x;
    if (i < n) atomicAdd(&cnt[dst[i]], 1.f);
}

__global__ void inv_kernel() {
    int i = blockIdx.x * blockDim.x + threadIdx.x;
    if (i < NN) {
        g_cntP[i] = 1.f / fmaxf(g_cntP[i], 1.f);
        g_cntN[i] = 1.f / fmaxf(g_cntN[i], 1.f);
    }
}

__global__ void copyx_kernel(const float* __restrict__ sgu, const float* __restrict__ sgi) {
    int i = blockIdx.x * blockDim.x + threadIdx.x;
    if (i < NU * D)      g_x[i] = sgu[i];
    else if (i < NN * D) g_x[i] = sgi[i - NU * D];
}

// layer-1 scatter: agg[dst, 0:64] += x[src, 0:64]   (16 threads x float4 per edge)
__global__ void scatter64(const int* __restrict__ src, const int* __restrict__ dst, int n,
                          const float* __restrict__ x, float* __restrict__ agg) {
    int t = blockIdx.x * blockDim.x + threadIdx.x;
    int e = t >> 4;
    if (e >= n) return;
    int c = (t & 15) * 4;
    int s = src[e], d = dst[e];
    float4 v = *(const float4*)&x[s * D + c];
    float* p = &agg[d * D + c];
    atomicAdd(p + 0, v.x); atomicAdd(p + 1, v.y);
    atomicAdd(p + 2, v.z); atomicAdd(p + 3, v.w);
}

// layers 2/3 pos-edge scatter: aggP[d,0:32]+=xp[s]; aggN[d,0:32]+=xn[s]
__global__ void scatter_split_pos(const int* __restrict__ src, const int* __restrict__ dst, int n,
                                  const float* __restrict__ z) {
    int t = blockIdx.x * blockDim.x + threadIdx.x;
    int e = t >> 4;
    if (e >= n) return;
    int q = t & 15;
    int s = src[e], d = dst[e];
    int c = (q & 7) * 4;
    if (q < 8) {
        float4 v = *(const float4*)&z[s * D + c];
        float* p = &g_aggP[d * D + c];
        atomicAdd(p + 0, v.x); atomicAdd(p + 1, v.y); atomicAdd(p + 2, v.z); atomicAdd(p + 3, v.w);
    } else {
        float4 v = *(const float4*)&z[s * D + 32 + c];
        float* p = &g_aggN[d * D + c];
        atomicAdd(p + 0, v.x); atomicAdd(p + 1, v.y); atomicAdd(p + 2, v.z); atomicAdd(p + 3, v.w);
    }
}

// layers 2/3 neg-edge scatter: aggP[d,32:64]+=xn[s]; aggN[d,32:64]+=xp[s]
__global__ void scatter_split_neg(const int* __restrict__ src, const int* __restrict__ dst, int n,
                                  const float* __restrict__ z) {
    int t = blockIdx.x * blockDim.x + threadIdx.x;
    int e = t >> 4;
    if (e >= n) return;
    int q = t & 15;
    int s = src[e], d = dst[e];
    int c = (q & 7) * 4;
    if (q < 8) {
        float4 v = *(const float4*)&z[s * D + 32 + c];
        float* p = &g_aggP[d * D + 32 + c];
        atomicAdd(p + 0, v.x); atomicAdd(p + 1, v.y); atomicAdd(p + 2, v.z); atomicAdd(p + 3, v.w);
    } else {
        float4 v = *(const float4*)&z[s * D + c];
        float* p = &g_aggN[d * D + 32 + c];
        atomicAdd(p + 0, v.x); atomicAdd(p + 1, v.y); atomicAdd(p + 2, v.z); atomicAdd(p + 3, v.w);
    }
}

// layer-1 transform: z = relu([meanP@pl + x@prw + prb , meanN@nl + x@nrw + nrb])
__global__ void transform1(const float* __restrict__ pl, const float* __restrict__ prw,
                           const float* __restrict__ prb,
                           const float* __restrict__ nl, const float* __restrict__ nrw,
                           const float* __restrict__ nrb, float* __restrict__ zout) {
    __shared__ float s_pl[D * H2], s_prw[D * H2], s_nl[D * H2], s_nrw[D * H2];
    for (int i = threadIdx.x; i < D * H2; i += 256) {
        s_pl[i] = pl[i]; s_prw[i] = prw[i]; s_nl[i] = nl[i]; s_nrw[i] = nrw[i];
    }
    __syncthreads();
    int node = blockIdx.x * 8 + (threadIdx.x >> 5);
    int c = threadIdx.x & 31;
    if (node >= NN) return;
    float invP = g_cntP[node], invN = g_cntN[node];
    float accP = prb[c], accN = nrb[c];
    const float* xr  = &g_x[node * D];
    const float* apr = &g_aggP[node * D];
    const float* anr = &g_aggN[node * D];
#pragma unroll 8
    for (int k = 0; k < D; k++) {
        float xv = xr[k];
        accP += (apr[k] * invP) * s_pl[k * H2 + c] + xv * s_prw[k * H2 + c];
        accN += (anr[k] * invN) * s_nl[k * H2 + c] + xv * s_nrw[k * H2 + c];
    }
    zout[node * D + c]      = fmaxf(accP, 0.f);
    zout[node * D + 32 + c] = fmaxf(accN, 0.f);
}

// layers 2/3 transform
__global__ void transform2(const float* __restrict__ pl, const float* __restrict__ prw,
                           const float* __restrict__ prb,
                           const float* __restrict__ nl, const float* __restrict__ nrw,
                           const float* __restrict__ nrb,
                           const float* __restrict__ zin, float* __restrict__ zout) {
    __shared__ float s_pl[D * H2], s_nl[D * H2], s_prw[H2 * H2], s_nrw[H2 * H2];
    for (int i = threadIdx.x; i < D * H2; i += 256) { s_pl[i] = pl[i]; s_nl[i] = nl[i]; }
    for (int i = threadIdx.x; i < H2 * H2; i += 256) { s_prw[i] = prw[i]; s_nrw[i] = nrw[i]; }
    __syncthreads();
    int node = blockIdx.x * 8 + (threadIdx.x >> 5);
    int c = threadIdx.x & 31;
    if (node >= NN) return;
    float invP = g_cntP[node], invN = g_cntN[node];
    float accP = prb[c], accN = nrb[c];
    const float* zr  = &zin[node * D];
    const float* apr = &g_aggP[node * D];
    const float* anr = &g_aggN[node * D];
#pragma unroll 8
    for (int k = 0; k < H2; k++) {
        float ap0 = apr[k] * invP, ap1 = apr[32 + k] * invN;
        float an0 = anr[k] * invP, an1 = anr[32 + k] * invN;
        float xp = zr[k], xn = zr[32 + k];
        accP += ap0 * s_pl[k * H2 + c] + ap1 * s_pl[(32 + k) * H2 + c] + xp * s_prw[k * H2 + c];
        accN += an0 * s_nl[k * H2 + c] + an1 * s_nl[(32 + k) * H2 + c] + xn * s_nrw[k * H2 + c];
    }
    zout[node * D + c]      = fmaxf(accP, 0.f);
    zout[node * D + 32 + c] = fmaxf(accN, 0.f);
}

// per-edge 3-class head -> mask_semantic
__global__ void class_kernel(const int* __restrict__ e0, const int* __restrict__ e1,
                             const float* __restrict__ z,
                             const float* __restrict__ lw, const float* __restrict__ lb) {
    __shared__ float slw[2 * D * 3];
    __shared__ float slb[3];
    for (int i = threadIdx.x; i < 2 * D * 3; i += 256) slw[i] = lw[i];
    if (threadIdx.x < 3) slb[threadIdx.x] = lb[threadIdx.x];
    __syncthreads();
    int warp = (blockIdx.x * blockDim.x + threadIdx.x) >> 5;
    int lane = threadIdx.x & 31;
    if (warp >= E) return;
    int a = e0[warp], b = e1[warp];
    float za0 = z[a * D + lane], za1 = z[a * D + 32 + lane];
    float zb0 = z[b * D + lane], zb1 = z[b * D + 32 + lane];
    float v0, v1, v2;
    {
        v0 = za0 * slw[lane * 3 + 0] + za1 * slw[(32 + lane) * 3 + 0]
           + zb0 * slw[(64 + lane) * 3 + 0] + zb1 * slw[(96 + lane) * 3 + 0];
        v1 = za0 * slw[lane * 3 + 1] + za1 * slw[(32 + lane) * 3 + 1]
           + zb0 * slw[(64 + lane) * 3 + 1] + zb1 * slw[(96 + lane) * 3 + 1];
        v2 = za0 * slw[lane * 3 + 2] + za1 * slw[(32 + lane) * 3 + 2]
           + zb0 * slw[(64 + lane) * 3 + 2] + zb1 * slw[(96 + lane) * 3 + 2];
    }
#pragma unroll
    for (int off = 16; off; off >>= 1) {
        v0 += __shfl_xor_sync(0xffffffffu, v0, off);
        v1 += __shfl_xor_sync(0xffffffffu, v1, off);
        v2 += __shfl_xor_sync(0xffffffffu, v2, off);
    }
    if (lane == 0) {
        v0 += slb[0]; v1 += slb[1]; v2 += slb[2];
        int cls = 0; float best = v0;
        if (v1 > best) { best = v1; cls = 1; }
        if (v2 > best) { cls = 2; }
        g_maskS[warp] = (float)(cls - 1);
    }
}

__global__ void sum_kernel() {
    float sf = 0.f, ss = 0.f;
    for (int i = blockIdx.x * blockDim.x + threadIdx.x; i < E; i += gridDim.x * blockDim.x) {
        sf += fabsf(g_maskF[i]);
        ss += fabsf(g_maskS[i]);
    }
#pragma unroll
    for (int off = 16; off; off >>= 1) {
        sf += __shfl_xor_sync(0xffffffffu, sf, off);
        ss += __shfl_xor_sync(0xffffffffu, ss, off);
    }
    __shared__ float shf[8], shs[8];
    int w = threadIdx.x >> 5, l = threadIdx.x & 31;
    if (l == 0) { shf[w] = sf; shs[w] = ss; }
    __syncthreads();
    if (threadIdx.x == 0) {
        float a = 0.f, b = 0.f;
        for (int i = 0; i < 8; i++) { a += shf[i]; b += shs[i]; }
        atomicAdd(&g_sums[0], a);
        atomicAdd(&g_sums[1], b);
    }
}

__global__ void wedge_kernel(const int* __restrict__ e0, const float* __restrict__ fw) {
    int i = blockIdx.x * blockDim.x + threadIdx.x;
    if (i >= E) return;
    float w0 = fw[0], w1 = fw[1], w2 = fw[2];
    float m = fmaxf(w0, fmaxf(w1, w2));
    float ex0 = expf(w0 - m), ex1 = expf(w1 - m), ex2 = expf(w2 - m);
    float s = ex0 + ex1 + ex2;
    float sw0 = ex0 / s, sw1 = ex1 / s, sw2 = ex2 / s;
    float nO = 1.f / (float)E;
    float nF = g_maskF[i] / fmaxf(g_sums[0], 1e-12f);
    float nS = g_maskS[i] / fmaxf(g_sums[1], 1e-12f);
    float fused = sw0 * nO + sw1 * nF + sw2 * nS;
    float w = (fused > 0.5f) ? 1.f : 0.f;
    g_we[i] = w;
    if (w != 0.f) atomicAdd(&g_deg[e0[i]], w);
}

__global__ void dis_kernel() {
    int i = blockIdx.x * blockDim.x + threadIdx.x;
    if (i < NN) {
        float d = g_deg[i];
        g_deg[i] = (d > 0.f) ? rsqrtf(fmaxf(d, 1e-12f)) : 0.f;
    }
}

__global__ void norm_kernel(const int* __restrict__ e0, const int* __restrict__ e1) {
    int i = blockIdx.x * blockDim.x + threadIdx.x;
    if (i >= E) return;
    g_norm[i] = g_deg[e0[i]] * g_we[i] * g_deg[e1[i]];
}

__global__ void initacc_kernel(const float* __restrict__ lgu, const float* __restrict__ lgi) {
    int i = blockIdx.x * blockDim.x + threadIdx.x;
    if (i >= NN * D) return;
    float v = (i < NU * D) ? lgu[i] : lgi[i - NU * D];
    g_acc[i] = v;
    g_xk[i]  = v;
}

__global__ void prop_kernel(const int* __restrict__ e0, const int* __restrict__ e1,
                            const float* __restrict__ xin, float* __restrict__ xout) {
    int t = blockIdx.x * blockDim.x + threadIdx.x;
    int e = t >> 4;
    if (e >= E) return;
    float nm = g_norm[e];
    if (nm == 0.f) return;
    int c = (t & 15) * 4;
    int s = e1[e], d = e0[e];
    float4 v = *(const float4*)&xin[s * D + c];
    float* p = &xout[d * D + c];
    atomicAdd(p + 0, nm * v.x); atomicAdd(p + 1, nm * v.y);
    atomicAdd(p + 2, nm * v.z); atomicAdd(p + 3, nm * v.w);
}

__global__ void accadd_kernel(const float* __restrict__ xnew) {
    int i = blockIdx.x * blockDim.x + threadIdx.x;
    if (i < NN * D) g_acc[i] += xnew[i];
}

__global__ void out_kernel(const float* __restrict__ lgu, const float* __restrict__ lgi,
                           float* __restrict__ out, int n) {
    int i = blockIdx.x * blockDim.x + threadIdx.x;
    if (i >= n) return;
    constexpr int A = NU * D;
    constexpr int C = NF * D;
    if (i < A)               out[i] = g_acc[i] * 0.25f;
    else if (i < 2 * A)      out[i] = lgu[i - A];
    else if (i < 2 * A + C)  out[i] = g_acc[A + (i - 2 * A)] * 0.25f;
    else                     out[i] = lgi[i - 2 * A - C];
}

// ---------------- launch ----------------
extern "C" void kernel_launch(void* const* d_in, const int* in_sizes, int n_in,
                              void* d_out, int out_size) {
    const float* user_feat = (const float*)d_in[0];
    const float* food_feat = (const float*)d_in[1];
    const int*   ei        = (const int*)d_in[2];
    const int*   pe        = (const int*)d_in[3];
    const int*   ne        = (const int*)d_in[4];
    const float* W_user    = (const float*)d_in[5];
    const float* b_user    = (const float*)d_in[6];
    const float* W_food    = (const float*)d_in[7];
    const float* b_food    = (const float*)d_in[8];
    const float* metric_w  = (const float*)d_in[9];
    const float* fusion_w  = (const float*)d_in[10];
    const float* sg_u      = (const float*)d_in[11];
    const float* sg_i      = (const float*)d_in[12];
    const float* c1_pl     = (const float*)d_in[13];
    const float* c1_prw    = (const float*)d_in[14];
    const float* c1_prb    = (const float*)d_in[15];
    const float* c1_nl     = (const float*)d_in[16];
    const float* c1_nrw    = (const float*)d_in[17];
    const float* c1_nrb    = (const float*)d_in[18];
    const float* cs_pl     = (const float*)d_in[19];
    const float* cs_prw    = (const float*)d_in[20];
    const float* cs_prb    = (const float*)d_in[21];
    const float* cs_nl     = (const float*)d_in[22];
    const float* cs_nrw    = (const float*)d_in[23];
    const float* cs_nrb    = (const float*)d_in[24];
    const float* lin_w     = (const float*)d_in[25];
    const float* lin_b     = (const float*)d_in[26];
    const float* lg_u      = (const float*)d_in[27];
    const float* lg_i      = (const float*)d_in[28];
    float* out = (float*)d_out;

    void *a_u, *a_f, *a_x, *a_y, *a_aggP, *a_aggN, *a_cntP, *a_cntN,
         *a_deg, *a_sums, *a_xk, *a_xk2;
    cudaGetSymbolAddress(&a_u, g_u);
    cudaGetSymbolAddress(&a_f, g_f);
    cudaGetSymbolAddress(&a_x, g_x);
    cudaGetSymbolAddress(&a_y, g_y);
    cudaGetSymbolAddress(&a_aggP, g_aggP);
    cudaGetSymbolAddress(&a_aggN, g_aggN);
    cudaGetSymbolAddress(&a_cntP, g_cntP);
    cudaGetSymbolAddress(&a_cntN, g_cntN);
    cudaGetSymbolAddress(&a_deg, g_deg);
    cudaGetSymbolAddress(&a_sums, g_sums);
    cudaGetSymbolAddress(&a_xk, g_xk);
    cudaGetSymbolAddress(&a_xk2, g_xk2);

    const int TPB = 256;
    const int gE      = (E + TPB - 1) / TPB;         // thread per edge
    const int gEw     = (E * 32 + TPB - 1) / TPB;    // warp per edge
    const int gE16    = (E * 16 + TPB - 1) / TPB;    // 16 threads per edge
    const int gN      = (NN + TPB - 1) / TPB;
    const int gND     = (NN * D + TPB - 1) / TPB;
    const int gNode8  = (NN + 7) / 8;

    // 1. feature GEMMs
    gemm_relu<<<(NU + 3) / 4, TPB>>>(user_feat, W_user, b_user, (float*)a_u, NU);
    gemm_relu<<<(NF + 3) / 4, TPB>>>(food_feat, W_food, b_food, (float*)a_f, NF);

    // 2. per-edge similarity -> mask_feature
    sim_kernel<<<gEw, TPB>>>(ei, ei + E, metric_w);

    // 3. segment counts (shared by all conv layers)
    cudaMemsetAsync(a_cntP, 0, NN * sizeof(float));
    cudaMemsetAsync(a_cntN, 0, NN * sizeof(float));
    count_kernel<<<(EP + TPB - 1) / TPB, TPB>>>(pe + EP, EP, (float*)a_cntP);
    count_kernel<<<(EN + TPB - 1) / TPB, TPB>>>(ne + EN, EN, (float*)a_cntN);
    inv_kernel<<<gN, TPB>>>();

    // 4. signed conv layer 1:  g_x (concat sg emb) -> g_y
    copyx_kernel<<<gND, TPB>>>(sg_u, sg_i);
    cudaMemsetAsync(a_aggP, 0, NN * D * sizeof(float));
    cudaMemsetAsync(a_aggN, 0, NN * D * sizeof(float));
    scatter64<<<gE16, TPB>>>(pe, pe + EP, EP, (const float*)a_x, (float*)a_aggP);
    scatter64<<<gE16, TPB>>>(ne, ne + EN, EN, (const float*)a_x, (float*)a_aggN);
    transform1<<<gNode8, TPB>>>(c1_pl, c1_prw, c1_prb, c1_nl, c1_nrw, c1_nrb, (float*)a_y);

    // 5. signed conv layers 2 & 3
    // layer 2: g_y -> g_x
    cudaMemsetAsync(a_aggP, 0, NN * D * sizeof(float));
    cudaMemsetAsync(a_aggN, 0, NN * D * sizeof(float));
    scatter_split_pos<<<gE16, TPB>>>(pe, pe + EP, EP, (const float*)a_y);
    scatter_split_neg<<<gE16, TPB>>>(ne, ne + EN, EN, (const float*)a_y);
    transform2<<<gNode8, TPB>>>(cs_pl, cs_prw, cs_prb, cs_nl, cs_nrw, cs_nrb,
                                (const float*)a_y, (float*)a_x);
    // layer 3: g_x -> g_y
    cudaMemsetAsync(a_aggP, 0, NN * D * sizeof(float));
    cudaMemsetAsync(a_aggN, 0, NN * D * sizeof(float));
    scatter_split_pos<<<gE16, TPB>>>(pe, pe + EP, EP, (const float*)a_x);
    scatter_split_neg<<<gE16, TPB>>>(ne, ne + EN, EN, (const float*)a_x);
    transform2<<<gNode8, TPB>>>(cs_pl + D * H2, cs_prw + H2 * H2, cs_prb + H2,
                                cs_nl + D * H2, cs_nrw + H2 * H2, cs_nrb + H2,
                                (const float*)a_x, (float*)a_y);

    // 6. per-edge classifier -> mask_semantic
    class_kernel<<<gEw, TPB>>>(ei, ei + E, (const float*)a_y, lin_w, lin_b);

    // 7. mask L1 sums, fused mask, degrees, norm
    cudaMemsetAsync(a_sums, 0, 2 * sizeof(float));
    sum_kernel<<<256, TPB>>>();
    cudaMemsetAsync(a_deg, 0, NN * sizeof(float));
    wedge_kernel<<<gE, TPB>>>(ei, fusion_w);
    dis_kernel<<<gN, TPB>>>();
    norm_kernel<<<gE, TPB>>>(ei, ei + E);

    // 8. LightGCN propagation (3 hops)
    initacc_kernel<<<gND, TPB>>>(lg_u, lg_i);
    float* cur = (float*)a_xk;
    float* nxt = (float*)a_xk2;
    for (int it = 0; it < 3; it++) {
        cudaMemsetAsync(nxt, 0, NN * D * sizeof(float));
        prop_kernel<<<gE16, TPB>>>(ei, ei + E, cur, nxt);
        accadd_kernel<<<gND, TPB>>>(nxt);
        float* t = cur; cur = nxt; nxt = t;
    }

    // 9. outputs
    out_kernel<<<(out_size + TPB - 1) / TPB, TPB>>>(lg_u, lg_i, out, out_size);
}

// round 3
// speedup vs baseline: 1.1266x; 1.1266x over previous
#include <cuda_runtime.h>
#include <math.h>

// ---------------- problem constants ----------------
constexpr int NU = 50000, NF = 50000, NN = 100000;
constexpr int D  = 64,    H2 = 32,    FU = 256;
constexpr int E  = 500000, EP = 500000, EN = 500000;
constexpr int NH = 4;
constexpr float THRESH = 0.3f;

// ---------------- device scratch (no allocs allowed) ----------------
__device__ float g_u[NU * D];
__device__ float g_f[NF * D];
__device__ float g_x[NN * D];      // conv ping
__device__ float g_y[NN * D];      // conv pong
__device__ float g_aggP[NN * D];
__device__ float g_aggN[NN * D];
__device__ float g_cntP[NN];       // becomes 1/max(cnt,1)
__device__ float g_cntN[NN];
__device__ float g_maskF[E];
__device__ float g_maskS[E];
__device__ float g_we[E];
__device__ float g_norm[E];
__device__ float g_deg[NN];        // becomes dis
__device__ float g_xk[NN * D];
__device__ float g_xk2[NN * D];
__device__ float g_acc[NN * D];
__device__ float g_sums[2];

// 128-bit global reduction: one RED.128 instead of four RED.32
__device__ __forceinline__ void red_add_v4(float* p, float x, float y, float z, float w) {
    asm volatile("red.global.add.v4.f32 [%0], {%1,%2,%3,%4};"
                 :: "l"(p), "f"(x), "f"(y), "f"(z), "f"(w) : "memory");
}

// ---------------- kernels ----------------

// out[row, c] = relu(dot(feat[row,:256], W[:,c]) + b[c]); 4 rows x 64 cols per block
__global__ void gemm_relu(const float* __restrict__ feat, const float* __restrict__ W,
                          const float* __restrict__ b, float* __restrict__ out, int rows) {
    __shared__ float sfeat[4][FU];
    int row0 = blockIdx.x * 4;
    for (int rr = 0; rr < 4; rr++) {
        int row = row0 + rr;
        if (row < rows)
            for (int k = threadIdx.x; k < FU; k += 256)
                sfeat[rr][k] = feat[row * FU + k];
    }
    __syncthreads();
    int c = threadIdx.x & 63;
    int r = threadIdx.x >> 6;
    int row = row0 + r;
    if (row >= rows) return;
    float acc = b[c];
#pragma unroll 8
    for (int k = 0; k < FU; k++)
        acc += sfeat[r][k] * W[k * D + c];
    out[row * D + c] = fmaxf(acc, 0.f);
}

// per-edge multi-head cosine similarity -> mask_feature
__global__ void sim_kernel(const int* __restrict__ e0, const int* __restrict__ e1,
                           const float* __restrict__ mw) {
    __shared__ float smw[NH * D];
    if (threadIdx.x < NH * D) smw[threadIdx.x] = mw[threadIdx.x];
    __syncthreads();
    int warp = (blockIdx.x * blockDim.x + threadIdx.x) >> 5;
    int lane = threadIdx.x & 31;
    if (warp >= E) return;
    int a = e0[warp], bn = e1[warp];
    float u0 = g_u[a * D + lane],  u1 = g_u[a * D + 32 + lane];
    float f0 = g_f[bn * D + lane], f1 = g_f[bn * D + 32 + lane];
    float sim = 0.f;
#pragma unroll
    for (int h = 0; h < NH; h++) {
        float w0 = smw[h * D + lane], w1 = smw[h * D + 32 + lane];
        float a0 = u0 * w0, a1 = u1 * w1, b0 = f0 * w0, b1 = f1 * w1;
        float ab = a0 * b0 + a1 * b1;
        float aa = a0 * a0 + a1 * a1;
        float bb = b0 * b0 + b1 * b1;
#pragma unroll
        for (int off = 16; off; off >>= 1) {
            ab += __shfl_xor_sync(0xffffffffu, ab, off);
            aa += __shfl_xor_sync(0xffffffffu, aa, off);
            bb += __shfl_xor_sync(0xffffffffu, bb, off);
        }
        sim += ab / (fmaxf(sqrtf(aa), 1e-8f) * fmaxf(sqrtf(bb), 1e-8f));
    }
    if (lane == 0) {
        sim *= (1.f / NH);
        g_maskF[warp] = (sim < THRESH) ? 0.f : sim;
    }
}

// counts for both edge sets in one launch
__global__ void count_kernel(const int* __restrict__ pdst, const int* __restrict__ ndst) {
    int i = blockIdx.x * blockDim.x + threadIdx.x;
    if (i < EP) atomicAdd(&g_cntP[pdst[i]], 1.f);
    else {
        i -= EP;
        if (i < EN) atomicAdd(&g_cntN[ndst[i]], 1.f);
    }
}

__global__ void inv_kernel() {
    int i = blockIdx.x * blockDim.x + threadIdx.x;
    if (i < NN) {
        g_cntP[i] = 1.f / fmaxf(g_cntP[i], 1.f);
        g_cntN[i] = 1.f / fmaxf(g_cntN[i], 1.f);
    }
}

__global__ void copyx_kernel(const float* __restrict__ sgu, const float* __restrict__ sgi) {
    int i = blockIdx.x * blockDim.x + threadIdx.x;
    if (i < NU * D)      g_x[i] = sgu[i];
    else if (i < NN * D) g_x[i] = sgi[i - NU * D];
}

// layer-1 scatter, both edge sets in one launch:
// aggP[dst,0:64] += x[src]  (pos edges);  aggN[dst,0:64] += x[src]  (neg edges)
__global__ void scatter64_both(const int* __restrict__ pe, const int* __restrict__ ne,
                               const float* __restrict__ x) {
    long long t = (long long)blockIdx.x * blockDim.x + threadIdx.x;
    int e = (int)(t >> 4);
    if (e >= EP + EN) return;
    int c = ((int)t & 15) * 4;
    const int* src; float* agg;
    if (e < EP) { src = pe; agg = g_aggP; }
    else        { e -= EP; src = ne; agg = g_aggN; }
    int s = src[e], d = src[e + EP];   // EP == EN, dst = src + E offset
    float4 v = *(const float4*)&x[s * D + c];
    red_add_v4(&agg[d * D + c], v.x, v.y, v.z, v.w);
}

// layers 2/3 scatter, both edge sets in one launch.
// pos edges: aggP[d,0:32]+=xp[s]; aggN[d,0:32]+=xn[s]
// neg edges: aggP[d,32:64]+=xn[s]; aggN[d,32:64]+=xp[s]
__global__ void scatter_split_both(const int* __restrict__ pe, const int* __restrict__ ne,
                                   const float* __restrict__ z) {
    long long t = (long long)blockIdx.x * blockDim.x + threadIdx.x;
    int e = (int)(t >> 4);
    if (e >= EP + EN) return;
    int q = (int)t & 15;
    int c = (q & 7) * 4;
    if (e < EP) {
        int s = pe[e], d = pe[e + EP];
        if (q < 8) {
            float4 v = *(const float4*)&z[s * D + c];
            red_add_v4(&g_aggP[d * D + c], v.x, v.y, v.z, v.w);
        } else {
            float4 v = *(const float4*)&z[s * D + 32 + c];
            red_add_v4(&g_aggN[d * D + c], v.x, v.y, v.z, v.w);
        }
    } else {
        e -= EP;
        int s = ne[e], d = ne[e + EN];
        if (q < 8) {
            float4 v = *(const float4*)&z[s * D + 32 + c];
            red_add_v4(&g_aggP[d * D + 32 + c], v.x, v.y, v.z, v.w);
        } else {
            float4 v = *(const float4*)&z[s * D + c];
            red_add_v4(&g_aggN[d * D + 32 + c], v.x, v.y, v.z, v.w);
        }
    }
}

// layer-1 transform: z = relu([meanP@pl + x@prw + prb , meanN@nl + x@nrw + nrb])
__global__ void transform1(const float* __restrict__ pl, const float* __restrict__ prw,
                           const float* __restrict__ prb,
                           const float* __restrict__ nl, const float* __restrict__ nrw,
                           const float* __restrict__ nrb, float* __restrict__ zout) {
    __shared__ float s_pl[D * H2], s_prw[D * H2], s_nl[D * H2], s_nrw[D * H2];
    for (int i = threadIdx.x; i < D * H2; i += 256) {
        s_pl[i] = pl[i]; s_prw[i] = prw[i]; s_nl[i] = nl[i]; s_nrw[i] = nrw[i];
    }
    __syncthreads();
    int node = blockIdx.x * 8 + (threadIdx.x >> 5);
    int c = threadIdx.x & 31;
    if (node >= NN) return;
    float invP = g_cntP[node], invN = g_cntN[node];
    float accP = prb[c], accN = nrb[c];
    const float* xr  = &g_x[node * D];
    const float* apr = &g_aggP[node * D];
    const float* anr = &g_aggN[node * D];
#pragma unroll 8
    for (int k = 0; k < D; k++) {
        float xv = xr[k];
        accP += (apr[k] * invP) * s_pl[k * H2 + c] + xv * s_prw[k * H2 + c];
        accN += (anr[k] * invN) * s_nl[k * H2 + c] + xv * s_nrw[k * H2 + c];
    }
    zout[node * D + c]      = fmaxf(accP, 0.f);
    zout[node * D + 32 + c] = fmaxf(accN, 0.f);
}

// layers 2/3 transform
__global__ void transform2(const float* __restrict__ pl, const float* __restrict__ prw,
                           const float* __restrict__ prb,
                           const float* __restrict__ nl, const float* __restrict__ nrw,
                           const float* __restrict__ nrb,
                           const float* __restrict__ zin, float* __restrict__ zout) {
    __shared__ float s_pl[D * H2], s_nl[D * H2], s_prw[H2 * H2], s_nrw[H2 * H2];
    for (int i = threadIdx.x; i < D * H2; i += 256) { s_pl[i] = pl[i]; s_nl[i] = nl[i]; }
    for (int i = threadIdx.x; i < H2 * H2; i += 256) { s_prw[i] = prw[i]; s_nrw[i] = nrw[i]; }
    __syncthreads();
    int node = blockIdx.x * 8 + (threadIdx.x >> 5);
    int c = threadIdx.x & 31;
    if (node >= NN) return;
    float invP = g_cntP[node], invN = g_cntN[node];
    float accP = prb[c], accN = nrb[c];
    const float* zr  = &zin[node * D];
    const float* apr = &g_aggP[node * D];
    const float* anr = &g_aggN[node * D];
#pragma unroll 8
    for (int k = 0; k < H2; k++) {
        float ap0 = apr[k] * invP, ap1 = apr[32 + k] * invN;
        float an0 = anr[k] * invP, an1 = anr[32 + k] * invN;
        float xp = zr[k], xn = zr[32 + k];
        accP += ap0 * s_pl[k * H2 + c] + ap1 * s_pl[(32 + k) * H2 + c] + xp * s_prw[k * H2 + c];
        accN += an0 * s_nl[k * H2 + c] + an1 * s_nl[(32 + k) * H2 + c] + xn * s_nrw[k * H2 + c];
    }
    zout[node * D + c]      = fmaxf(accP, 0.f);
    zout[node * D + 32 + c] = fmaxf(accN, 0.f);
}

// per-edge 3-class head -> mask_semantic
__global__ void class_kernel(const int* __restrict__ e0, const int* __restrict__ e1,
                             const float* __restrict__ z,
                             const float* __restrict__ lw, const float* __restrict__ lb) {
    __shared__ float slw[2 * D * 3];
    __shared__ float slb[3];
    for (int i = threadIdx.x; i < 2 * D * 3; i += 256) slw[i] = lw[i];
    if (threadIdx.x < 3) slb[threadIdx.x] = lb[threadIdx.x];
    __syncthreads();
    int warp = (blockIdx.x * blockDim.x + threadIdx.x) >> 5;
    int lane = threadIdx.x & 31;
    if (warp >= E) return;
    int a = e0[warp], b = e1[warp];
    float za0 = z[a * D + lane], za1 = z[a * D + 32 + lane];
    float zb0 = z[b * D + lane], zb1 = z[b * D + 32 + lane];
    float v0, v1, v2;
    {
        v0 = za0 * slw[lane * 3 + 0] + za1 * slw[(32 + lane) * 3 + 0]
           + zb0 * slw[(64 + lane) * 3 + 0] + zb1 * slw[(96 + lane) * 3 + 0];
        v1 = za0 * slw[lane * 3 + 1] + za1 * slw[(32 + lane) * 3 + 1]
           + zb0 * slw[(64 + lane) * 3 + 1] + zb1 * slw[(96 + lane) * 3 + 1];
        v2 = za0 * slw[lane * 3 + 2] + za1 * slw[(32 + lane) * 3 + 2]
           + zb0 * slw[(64 + lane) * 3 + 2] + zb1 * slw[(96 + lane) * 3 + 2];
    }
#pragma unroll
    for (int off = 16; off; off >>= 1) {
        v0 += __shfl_xor_sync(0xffffffffu, v0, off);
        v1 += __shfl_xor_sync(0xffffffffu, v1, off);
        v2 += __shfl_xor_sync(0xffffffffu, v2, off);
    }
    if (lane == 0) {
        v0 += slb[0]; v1 += slb[1]; v2 += slb[2];
        int cls = 0; float best = v0;
        if (v1 > best) { best = v1; cls = 1; }
        if (v2 > best) { cls = 2; }
        g_maskS[warp] = (float)(cls - 1);
    }
}

__global__ void sum_kernel() {
    float sf = 0.f, ss = 0.f;
    for (int i = blockIdx.x * blockDim.x + threadIdx.x; i < E; i += gridDim.x * blockDim.x) {
        sf += fabsf(g_maskF[i]);
        ss += fabsf(g_maskS[i]);
    }
#pragma unroll
    for (int off = 16; off; off >>= 1) {
        sf += __shfl_xor_sync(0xffffffffu, sf, off);
        ss += __shfl_xor_sync(0xffffffffu, ss, off);
    }
    __shared__ float shf[8], shs[8];
    int w = threadIdx.x >> 5, l = threadIdx.x & 31;
    if (l == 0) { shf[w] = sf; shs[w] = ss; }
    __syncthreads();
    if (threadIdx.x == 0) {
        float a = 0.f, b = 0.f;
        for (int i = 0; i < 8; i++) { a += shf[i]; b += shs[i]; }
        atomicAdd(&g_sums[0], a);
        atomicAdd(&g_sums[1], b);
    }
}

__global__ void wedge_kernel(const int* __restrict__ e0, const float* __restrict__ fw) {
    int i = blockIdx.x * blockDim.x + threadIdx.x;
    if (i >= E) return;
    float w0 = fw[0], w1 = fw[1], w2 = fw[2];
    float m = fmaxf(w0, fmaxf(w1, w2));
    float ex0 = expf(w0 - m), ex1 = expf(w1 - m), ex2 = expf(w2 - m);
    float s = ex0 + ex1 + ex2;
    float sw0 = ex0 / s, sw1 = ex1 / s, sw2 = ex2 / s;
    float nO = 1.f / (float)E;
    float nF = g_maskF[i] / fmaxf(g_sums[0], 1e-12f);
    float nS = g_maskS[i] / fmaxf(g_sums[1], 1e-12f);
    float fused = sw0 * nO + sw1 * nF + sw2 * nS;
    float w = (fused > 0.5f) ? 1.f : 0.f;
    g_we[i] = w;
    if (w != 0.f) atomicAdd(&g_deg[e0[i]], w);
}

__global__ void dis_kernel() {
    int i = blockIdx.x * blockDim.x + threadIdx.x;
    if (i < NN) {
        float d = g_deg[i];
        g_deg[i] = (d > 0.f) ? rsqrtf(fmaxf(d, 1e-12f)) : 0.f;
    }
}

__global__ void norm_kernel(const int* __restrict__ e0, const int* __restrict__ e1) {
    int i = blockIdx.x * blockDim.x + threadIdx.x;
    if (i >= E) return;
    g_norm[i] = g_deg[e0[i]] * g_we[i] * g_deg[e1[i]];
}

__global__ void initacc_kernel(const float* __restrict__ lgu, const float* __restrict__ lgi) {
    int i = blockIdx.x * blockDim.x + threadIdx.x;
    if (i >= NN * D) return;
    float v = (i < NU * D) ? lgu[i] : lgi[i - NU * D];
    g_acc[i] = v;
    g_xk[i]  = v;
}

__global__ void prop_kernel(const int* __restrict__ e0, const int* __restrict__ e1,
                            const float* __restrict__ xin, float* __restrict__ xout) {
    int t = blockIdx.x * blockDim.x + threadIdx.x;
    int e = t >> 4;
    if (e >= E) return;
    float nm = g_norm[e];
    if (nm == 0.f) return;
    int c = (t & 15) * 4;
    int s = e1[e], d = e0[e];
    float4 v = *(const float4*)&xin[s * D + c];
    red_add_v4(&xout[d * D + c], nm * v.x, nm * v.y, nm * v.z, nm * v.w);
}

__global__ void accadd_kernel(const float* __restrict__ xnew) {
    int i = blockIdx.x * blockDim.x + threadIdx.x;
    if (i < NN * D) g_acc[i] += xnew[i];
}

__global__ void out_kernel(const float* __restrict__ lgu, const float* __restrict__ lgi,
                           float* __restrict__ out, int n) {
    int i = blockIdx.x * blockDim.x + threadIdx.x;
    if (i >= n) return;
    constexpr int A = NU * D;
    constexpr int C = NF * D;
    if (i < A)               out[i] = g_acc[i] * 0.25f;
    else if (i < 2 * A)      out[i] = lgu[i - A];
    else if (i < 2 * A + C)  out[i] = g_acc[A + (i - 2 * A)] * 0.25f;
    else                     out[i] = lgi[i - 2 * A - C];
}

// ---------------- launch ----------------
extern "C" void kernel_launch(void* const* d_in, const int* in_sizes, int n_in,
                              void* d_out, int out_size) {
    const float* user_feat = (const float*)d_in[0];
    const float* food_feat = (const float*)d_in[1];
    const int*   ei        = (const int*)d_in[2];
    const int*   pe        = (const int*)d_in[3];
    const int*   ne        = (const int*)d_in[4];
    const float* W_user    = (const float*)d_in[5];
    const float* b_user    = (const float*)d_in[6];
    const float* W_food    = (const float*)d_in[7];
    const float* b_food    = (const float*)d_in[8];
    const float* metric_w  = (const float*)d_in[9];
    const float* fusion_w  = (const float*)d_in[10];
    const float* sg_u      = (const float*)d_in[11];
    const float* sg_i      = (const float*)d_in[12];
    const float* c1_pl     = (const float*)d_in[13];
    const float* c1_prw    = (const float*)d_in[14];
    const float* c1_prb    = (const float*)d_in[15];
    const float* c1_nl     = (const float*)d_in[16];
    const float* c1_nrw    = (const float*)d_in[17];
    const float* c1_nrb    = (const float*)d_in[18];
    const float* cs_pl     = (const float*)d_in[19];
    const float* cs_prw    = (const float*)d_in[20];
    const float* cs_prb    = (const float*)d_in[21];
    const float* cs_nl     = (const float*)d_in[22];
    const float* cs_nrw    = (const float*)d_in[23];
    const float* cs_nrb    = (const float*)d_in[24];
    const float* lin_w     = (const float*)d_in[25];
    const float* lin_b     = (const float*)d_in[26];
    const float* lg_u      = (const float*)d_in[27];
    const float* lg_i      = (const float*)d_in[28];
    float* out = (float*)d_out;

    void *a_u, *a_f, *a_x, *a_y, *a_aggP, *a_aggN, *a_cntP, *a_cntN,
         *a_deg, *a_sums, *a_xk, *a_xk2;
    cudaGetSymbolAddress(&a_u, g_u);
    cudaGetSymbolAddress(&a_f, g_f);
    cudaGetSymbolAddress(&a_x, g_x);
    cudaGetSymbolAddress(&a_y, g_y);
    cudaGetSymbolAddress(&a_aggP, g_aggP);
    cudaGetSymbolAddress(&a_aggN, g_aggN);
    cudaGetSymbolAddress(&a_cntP, g_cntP);
    cudaGetSymbolAddress(&a_cntN, g_cntN);
    cudaGetSymbolAddress(&a_deg, g_deg);
    cudaGetSymbolAddress(&a_sums, g_sums);
    cudaGetSymbolAddress(&a_xk, g_xk);
    cudaGetSymbolAddress(&a_xk2, g_xk2);

    const int TPB = 256;
    const int gE      = (E + TPB - 1) / TPB;                 // thread per edge
    const int gEw     = (E * 32 + TPB - 1) / TPB;            // warp per edge
    const int gE16    = (E * 16 + TPB - 1) / TPB;            // 16 threads per edge
    const long long both = (long long)(EP + EN) * 16;
    const int gB16    = (int)((both + TPB - 1) / TPB);       // both edge sets
    const int gN      = (NN + TPB - 1) / TPB;
    const int gND     = (NN * D + TPB - 1) / TPB;
    const int gNode8  = (NN + 7) / 8;

    // 1. feature GEMMs
    gemm_relu<<<(NU + 3) / 4, TPB>>>(user_feat, W_user, b_user, (float*)a_u, NU);
    gemm_relu<<<(NF + 3) / 4, TPB>>>(food_feat, W_food, b_food, (float*)a_f, NF);

    // 2. per-edge similarity -> mask_feature
    sim_kernel<<<gEw, TPB>>>(ei, ei + E, metric_w);

    // 3. segment counts (shared by all conv layers)
    cudaMemsetAsync(a_cntP, 0, NN * sizeof(float));
    cudaMemsetAsync(a_cntN, 0, NN * sizeof(float));
    count_kernel<<<(EP + EN + TPB - 1) / TPB, TPB>>>(pe + EP, ne + EN);
    inv_kernel<<<gN, TPB>>>();

    // 4. signed conv layer 1:  g_x (concat sg emb) -> g_y
    copyx_kernel<<<gND, TPB>>>(sg_u, sg_i);
    cudaMemsetAsync(a_aggP, 0, NN * D * sizeof(float));
    cudaMemsetAsync(a_aggN, 0, NN * D * sizeof(float));
    scatter64_both<<<gB16, TPB>>>(pe, ne, (const float*)a_x);
    transform1<<<gNode8, TPB>>>(c1_pl, c1_prw, c1_prb, c1_nl, c1_nrw, c1_nrb, (float*)a_y);

    // 5. signed conv layers 2 & 3
    // layer 2: g_y -> g_x
    cudaMemsetAsync(a_aggP, 0, NN * D * sizeof(float));
    cudaMemsetAsync(a_aggN, 0, NN * D * sizeof(float));
    scatter_split_both<<<gB16, TPB>>>(pe, ne, (const float*)a_y);
    transform2<<<gNode8, TPB>>>(cs_pl, cs_prw, cs_prb, cs_nl, cs_nrw, cs_nrb,
                                (const float*)a_y, (float*)a_x);
    // layer 3: g_x -> g_y
    cudaMemsetAsync(a_aggP, 0, NN * D * sizeof(float));
    cudaMemsetAsync(a_aggN, 0, NN * D * sizeof(float));
    scatter_split_both<<<gB16, TPB>>>(pe, ne, (const float*)a_x);
    transform2<<<gNode8, TPB>>>(cs_pl + D * H2, cs_prw + H2 * H2, cs_prb + H2,
                                cs_nl + D * H2, cs_nrw + H2 * H2, cs_nrb + H2,
                                (const float*)a_x, (float*)a_y);

    // 6. per-edge classifier -> mask_semantic
    class_kernel<<<gEw, TPB>>>(ei, ei + E, (const float*)a_y, lin_w, lin_b);

    // 7. mask L1 sums, fused mask, degrees, norm
    cudaMemsetAsync(a_sums, 0, 2 * sizeof(float));
    sum_kernel<<<256, TPB>>>();
    cudaMemsetAsync(a_deg, 0, NN * sizeof(float));
    wedge_kernel<<<gE, TPB>>>(ei, fusion_w);
    dis_kernel<<<gN, TPB>>>();
    norm_kernel<<<gE, TPB>>>(ei, ei + E);

    // 8. LightGCN propagation (3 hops)
    initacc_kernel<<<gND, TPB>>>(lg_u, lg_i);
    float* cur = (float*)a_xk;
    float* nxt = (float*)a_xk2;
    for (int it = 0; it < 3; it++) {
        cudaMemsetAsync(nxt, 0, NN * D * sizeof(float));
        prop_kernel<<<gE16, TPB>>>(ei, ei + E, cur, nxt);
        accadd_kernel<<<gND, TPB>>>(nxt);
        float* t = cur; cur = nxt; nxt = t;
    }

    // 9. outputs
    out_kernel<<<(out_size + TPB - 1) / TPB, TPB>>>(lg_u, lg_i, out, out_size);
}

// round 4
// speedup vs baseline: 1.6527x; 1.4670x over previous
#include <cuda_runtime.h>
#include <math.h>

// ---------------- problem constants ----------------
constexpr int NU = 50000, NF = 50000, NN = 100000;
constexpr int D  = 64,    H2 = 32,    FU = 256;
constexpr int E  = 500000, EP = 500000, EN = 500000;
constexpr int NH = 4;
constexpr float THRESH = 0.3f;

// ---------------- device scratch (no allocs allowed) ----------------
__device__ float g_u[NU * D];
__device__ float g_f[NF * D];
__device__ float g_x[NN * D];      // conv ping
__device__ float g_y[NN * D];      // conv pong
__device__ float g_maskF[E];
__device__ float g_maskS[E];
__device__ float g_we[E];
__device__ float g_norm[E];
__device__ float g_deg[NN];        // becomes dis
__device__ float g_xk[NN * D];
__device__ float g_xk2[NN * D];
__device__ float g_acc[NN * D];
__device__ float g_sums[2];
__device__ float4 g_nau[NU];       // per-user per-head norms
__device__ float4 g_naf[NF];       // per-food per-head norms
// CSR scratch
__device__ int g_cnt2[2 * NN];     // [0:NN]=pos in-degree, [NN:2NN]=neg
__device__ int g_ptr2[2 * NN];     // exclusive scan of cnt2
__device__ int g_fill2[2 * NN];
__device__ int g_bsum[256];
__device__ int g_csrP[EP];         // src node per pos edge, grouped by dst
__device__ int g_csrN[EN];

// ---------------- GEMM: 64x64 tile, 4x4 per thread ----------------
__global__ void gemm_relu_t(const float* __restrict__ feat, const float* __restrict__ W,
                            const float* __restrict__ bias, float* __restrict__ out, int rows) {
    __shared__ float sA[32][68];   // sA[k][r], 68 keeps float4 alignment
    __shared__ float sB[32][64];   // sB[k][c]
    int tid = threadIdx.x;
    int tx = tid & 15, ty = tid >> 4;
    int row0 = blockIdx.x * 64;
    float acc[4][4];
#pragma unroll
    for (int i = 0; i < 4; i++)
#pragma unroll
        for (int j = 0; j < 4; j++) acc[i][j] = 0.f;

    for (int k0 = 0; k0 < FU; k0 += 32) {
        // load feat chunk transposed: thread -> row r = tid/4, 8 k at kk=(tid%4)*8
        int r = tid >> 2;
        int kk = (tid & 3) * 8;
        int grow = row0 + r;
        float4 v0, v1;
        if (grow < rows) {
            const float4* src = (const float4*)&feat[grow * FU + k0 + kk];
            v0 = src[0]; v1 = src[1];
        } else {
            v0 = make_float4(0.f, 0.f, 0.f, 0.f); v1 = v0;
        }
        sA[kk + 0][r] = v0.x; sA[kk + 1][r] = v0.y; sA[kk + 2][r] = v0.z; sA[kk + 3][r] = v0.w;
        sA[kk + 4][r] = v1.x; sA[kk + 5][r] = v1.y; sA[kk + 6][r] = v1.z; sA[kk + 7][r] = v1.w;
        // load W chunk: linear copy
        {
            int idx = tid * 8;
            int kw = idx >> 6, cw = idx & 63;
            const float4* ws = (const float4*)&W[(k0 + kw) * D + cw];
            *(float4*)&sB[kw][cw]     = ws[0];
            *(float4*)&sB[kw][cw + 4] = ws[1];
        }
        __syncthreads();
#pragma unroll
        for (int k = 0; k < 32; k++) {
            float4 a = *(float4*)&sA[k][ty * 4];
            float4 b = *(float4*)&sB[k][tx * 4];
            acc[0][0] += a.x * b.x; acc[0][1] += a.x * b.y; acc[0][2] += a.x * b.z; acc[0][3] += a.x * b.w;
            acc[1][0] += a.y * b.x; acc[1][1] += a.y * b.y; acc[1][2] += a.y * b.z; acc[1][3] += a.y * b.w;
            acc[2][0] += a.z * b.x; acc[2][1] += a.z * b.y; acc[2][2] += a.z * b.z; acc[2][3] += a.z * b.w;
            acc[3][0] += a.w * b.x; acc[3][1] += a.w * b.y; acc[3][2] += a.w * b.z; acc[3][3] += a.w * b.w;
        }
        __syncthreads();
    }
    float4 bb = *(const float4*)&bias[tx * 4];
#pragma unroll
    for (int i = 0; i < 4; i++) {
        int grow = row0 + ty * 4 + i;
        if (grow < rows) {
            float4 o;
            o.x = fmaxf(acc[i][0] + bb.x, 0.f);
            o.y = fmaxf(acc[i][1] + bb.y, 0.f);
            o.z = fmaxf(acc[i][2] + bb.z, 0.f);
            o.w = fmaxf(acc[i][3] + bb.w, 0.f);
            *(float4*)&out[grow * D + tx * 4] = o;
        }
    }
}

// ---------------- per-node per-head norms for cosine sim ----------------
__global__ void node_norms(const float* __restrict__ x, const float* __restrict__ mw,
                           float4* __restrict__ out, int n) {
    __shared__ float smw[NH * D];
    if (threadIdx.x < NH * D) smw[threadIdx.x] = mw[threadIdx.x];
    __syncthreads();
    int warp = (blockIdx.x * blockDim.x + threadIdx.x) >> 5;
    int lane = threadIdx.x & 31;
    if (warp >= n) return;
    float x0 = x[warp * D + lane], x1 = x[warp * D + 32 + lane];
    float s[NH];
#pragma unroll
    for (int h = 0; h < NH; h++) {
        float a0 = x0 * smw[h * D + lane];
        float a1 = x1 * smw[h * D + 32 + lane];
        s[h] = a0 * a0 + a1 * a1;
    }
#pragma unroll
    for (int off = 16; off; off >>= 1)
#pragma unroll
        for (int h = 0; h < NH; h++) s[h] += __shfl_xor_sync(0xffffffffu, s[h], off);
    if (lane == 0)
        out[warp] = make_float4(fmaxf(sqrtf(s[0]), 1e-8f), fmaxf(sqrtf(s[1]), 1e-8f),
                                fmaxf(sqrtf(s[2]), 1e-8f), fmaxf(sqrtf(s[3]), 1e-8f));
}

// per-edge multi-head cosine similarity -> mask_feature
__global__ void sim_kernel(const int* __restrict__ e0, const int* __restrict__ e1,
                           const float* __restrict__ mw) {
    __shared__ float smw2[NH * D];
    if (threadIdx.x < NH * D) { float w = mw[threadIdx.x]; smw2[threadIdx.x] = w * w; }
    __syncthreads();
    int warp = (blockIdx.x * blockDim.x + threadIdx.x) >> 5;
    int lane = threadIdx.x & 31;
    if (warp >= E) return;
    int a = e0[warp], b = e1[warp];
    float u0 = g_u[a * D + lane],  u1 = g_u[a * D + 32 + lane];
    float f0 = g_f[b * D + lane],  f1 = g_f[b * D + 32 + lane];
    float p0 = u0 * f0, p1 = u1 * f1;
    float d[NH];
#pragma unroll
    for (int h = 0; h < NH; h++)
        d[h] = p0 * smw2[h * D + lane] + p1 * smw2[h * D + 32 + lane];
#pragma unroll
    for (int off = 16; off; off >>= 1)
#pragma unroll
        for (int h = 0; h < NH; h++) d[h] += __shfl_xor_sync(0xffffffffu, d[h], off);
    if (lane == 0) {
        float4 na = g_nau[a], nb = g_naf[b];
        float sim = d[0] / (na.x * nb.x) + d[1] / (na.y * nb.y)
                  + d[2] / (na.z * nb.z) + d[3] / (na.w * nb.w);
        sim *= (1.f / NH);
        g_maskF[warp] = (sim < THRESH) ? 0.f : sim;
    }
}

// ---------------- CSR build ----------------
__global__ void hist_kernel(const int* __restrict__ pd, const int* __restrict__ nd) {
    int i = blockIdx.x * blockDim.x + threadIdx.x;
    if (i < EP) atomicAdd(&g_cnt2[pd[i]], 1);
    else {
        i -= EP;
        if (i < EN) atomicAdd(&g_cnt2[NN + nd[i]], 1);
    }
}

__global__ void scan1_kernel() {
    __shared__ int sh[1024];
    int i = blockIdx.x * 1024 + threadIdx.x;
    int v = (i < 2 * NN) ? g_cnt2[i] : 0;
    sh[threadIdx.x] = v;
    __syncthreads();
    for (int off = 1; off < 1024; off <<= 1) {
        int t = (threadIdx.x >= off) ? sh[threadIdx.x - off] : 0;
        __syncthreads();
        sh[threadIdx.x] += t;
        __syncthreads();
    }
    if (i < 2 * NN) g_ptr2[i] = sh[threadIdx.x] - v;   // exclusive within block
    if (threadIdx.x == 1023) g_bsum[blockIdx.x] = sh[1023];
}

__global__ void scan2_kernel(int nb) {
    __shared__ int sh[256];
    int v = (threadIdx.x < nb) ? g_bsum[threadIdx.x] : 0;
    sh[threadIdx.x] = v;
    __syncthreads();
    for (int off = 1; off < 256; off <<= 1) {
        int t = (threadIdx.x >= off) ? sh[threadIdx.x - off] : 0;
        __syncthreads();
        sh[threadIdx.x] += t;
        __syncthreads();
    }
    if (threadIdx.x < nb) g_bsum[threadIdx.x] = sh[threadIdx.x] - v;  // exclusive
}

__global__ void scan3_kernel() {
    int i = blockIdx.x * blockDim.x + threadIdx.x;
    if (i < 2 * NN) g_ptr2[i] += g_bsum[i >> 10];
}

__global__ void fill_csr(const int* __restrict__ pe, const int* __restrict__ ne) {
    int i = blockIdx.x * blockDim.x + threadIdx.x;
    if (i < EP) {
        int d = pe[EP + i];
        int slot = atomicAdd(&g_fill2[d], 1);
        g_csrP[g_ptr2[d] + slot] = pe[i];
    } else {
        i -= EP;
        if (i < EN) {
            int d = ne[EN + i];
            int slot = atomicAdd(&g_fill2[NN + d], 1);
            g_csrN[(g_ptr2[NN + d] - EP) + slot] = ne[i];
        }
    }
}

// ---------------- fused conv layer 1 (gather + mean + transform) ----------------
__global__ void conv1_fused(const float* __restrict__ pl, const float* __restrict__ prw,
                            const float* __restrict__ prb,
                            const float* __restrict__ nl, const float* __restrict__ nrw,
                            const float* __restrict__ nrb) {
    __shared__ float s_pl[D * H2], s_prw[D * H2], s_nl[D * H2], s_nrw[D * H2];
    __shared__ float stage[8 * 192];
    for (int i = threadIdx.x; i < D * H2; i += 256) {
        s_pl[i] = pl[i]; s_prw[i] = prw[i]; s_nl[i] = nl[i]; s_nrw[i] = nrw[i];
    }
    __syncthreads();
    int w = threadIdx.x >> 5, c = threadIdx.x & 31;
    int node = blockIdx.x * 8 + w;
    if (node >= NN) return;
    int p0 = g_ptr2[node], p1 = g_ptr2[node + 1];
    int n0 = g_ptr2[NN + node] - EP;
    int n1 = ((node == NN - 1) ? EN : (g_ptr2[NN + node + 1] - EP));
    float mp0 = 0.f, mp1 = 0.f, mn0 = 0.f, mn1 = 0.f;
    for (int j = p0; j < p1; j++) {
        int s = g_csrP[j];
        mp0 += g_x[s * D + c]; mp1 += g_x[s * D + 32 + c];
    }
    for (int j = n0; j < n1; j++) {
        int s = g_csrN[j];
        mn0 += g_x[s * D + c]; mn1 += g_x[s * D + 32 + c];
    }
    float invP = 1.f / fmaxf((float)(p1 - p0), 1.f);
    float invN = 1.f / fmaxf((float)(n1 - n0), 1.f);
    float* st = &stage[w * 192];
    st[c]       = mp0 * invP; st[32 + c]  = mp1 * invP;
    st[64 + c]  = mn0 * invN; st[96 + c]  = mn1 * invN;
    st[128 + c] = g_x[node * D + c];
    st[160 + c] = g_x[node * D + 32 + c];
    __syncwarp();
    float accP = prb[c], accN = nrb[c];
#pragma unroll 8
    for (int k = 0; k < D; k++) {
        float mpk = st[k], mnk = st[64 + k], xk = st[128 + k];
        accP += mpk * s_pl[k * H2 + c] + xk * s_prw[k * H2 + c];
        accN += mnk * s_nl[k * H2 + c] + xk * s_nrw[k * H2 + c];
    }
    g_y[node * D + c]      = fmaxf(accP, 0.f);
    g_y[node * D + 32 + c] = fmaxf(accN, 0.f);
}

// ---------------- fused conv layers 2/3 ----------------
__global__ void conv2_fused(const float* __restrict__ pl, const float* __restrict__ prw,
                            const float* __restrict__ prb,
                            const float* __restrict__ nl, const float* __restrict__ nrw,
                            const float* __restrict__ nrb,
                            const float* __restrict__ zin, float* __restrict__ zout) {
    __shared__ float s_pl[D * H2], s_nl[D * H2], s_prw[H2 * H2], s_nrw[H2 * H2];
    __shared__ float stage[8 * 192];
    for (int i = threadIdx.x; i < D * H2; i += 256) { s_pl[i] = pl[i]; s_nl[i] = nl[i]; }
    for (int i = threadIdx.x; i < H2 * H2; i += 256) { s_prw[i] = prw[i]; s_nrw[i] = nrw[i]; }
    __syncthreads();
    int w = threadIdx.x >> 5, c = threadIdx.x & 31;
    int node = blockIdx.x * 8 + w;
    if (node >= NN) return;
    int p0 = g_ptr2[node], p1 = g_ptr2[node + 1];
    int n0 = g_ptr2[NN + node] - EP;
    int n1 = ((node == NN - 1) ? EN : (g_ptr2[NN + node + 1] - EP));
    float pp = 0.f, pn = 0.f, np_ = 0.f, nn = 0.f;
    for (int j = p0; j < p1; j++) {
        int s = g_csrP[j];
        pp += zin[s * D + c]; pn += zin[s * D + 32 + c];
    }
    for (int j = n0; j < n1; j++) {
        int s = g_csrN[j];
        np_ += zin[s * D + c]; nn += zin[s * D + 32 + c];
    }
    float invP = 1.f / fmaxf((float)(p1 - p0), 1.f);
    float invN = 1.f / fmaxf((float)(n1 - n0), 1.f);
    float* st = &stage[w * 192];
    st[c]       = pp * invP;  st[32 + c] = nn * invN;   // ap
    st[64 + c]  = pn * invP;  st[96 + c] = np_ * invN;  // an
    st[128 + c] = zin[node * D + c];                    // xp
    st[160 + c] = zin[node * D + 32 + c];               // xn
    __syncwarp();
    float accP = prb[c], accN = nrb[c];
#pragma unroll 8
    for (int k = 0; k < D; k++) {
        accP += st[k]      * s_pl[k * H2 + c];
        accN += st[64 + k] * s_nl[k * H2 + c];
    }
#pragma unroll 8
    for (int k = 0; k < H2; k++) {
        accP += st[128 + k] * s_prw[k * H2 + c];
        accN += st[160 + k] * s_nrw[k * H2 + c];
    }
    zout[node * D + c]      = fmaxf(accP, 0.f);
    zout[node * D + 32 + c] = fmaxf(accN, 0.f);
}

// ---------------- misc kernels ----------------
__global__ void copyx_kernel(const float* __restrict__ sgu, const float* __restrict__ sgi) {
    int i = blockIdx.x * blockDim.x + threadIdx.x;
    if (i < NU * D)      g_x[i] = sgu[i];
    else if (i < NN * D) g_x[i] = sgi[i - NU * D];
}

__global__ void class_kernel(const int* __restrict__ e0, const int* __restrict__ e1,
                             const float* __restrict__ z,
                             const float* __restrict__ lw, const float* __restrict__ lb) {
    __shared__ float slw[2 * D * 3];
    __shared__ float slb[3];
    for (int i = threadIdx.x; i < 2 * D * 3; i += 256) slw[i] = lw[i];
    if (threadIdx.x < 3) slb[threadIdx.x] = lb[threadIdx.x];
    __syncthreads();
    int warp = (blockIdx.x * blockDim.x + threadIdx.x) >> 5;
    int lane = threadIdx.x & 31;
    if (warp >= E) return;
    int a = e0[warp], b = e1[warp];
    float za0 = z[a * D + lane], za1 = z[a * D + 32 + lane];
    float zb0 = z[b * D + lane], zb1 = z[b * D + 32 + lane];
    float v0 = za0 * slw[lane * 3 + 0] + za1 * slw[(32 + lane) * 3 + 0]
             + zb0 * slw[(64 + lane) * 3 + 0] + zb1 * slw[(96 + lane) * 3 + 0];
    float v1 = za0 * slw[lane * 3 + 1] + za1 * slw[(32 + lane) * 3 + 1]
             + zb0 * slw[(64 + lane) * 3 + 1] + zb1 * slw[(96 + lane) * 3 + 1];
    float v2 = za0 * slw[lane * 3 + 2] + za1 * slw[(32 + lane) * 3 + 2]
             + zb0 * slw[(64 + lane) * 3 + 2] + zb1 * slw[(96 + lane) * 3 + 2];
#pragma unroll
    for (int off = 16; off; off >>= 1) {
        v0 += __shfl_xor_sync(0xffffffffu, v0, off);
        v1 += __shfl_xor_sync(0xffffffffu, v1, off);
        v2 += __shfl_xor_sync(0xffffffffu, v2, off);
    }
    if (lane == 0) {
        v0 += slb[0]; v1 += slb[1]; v2 += slb[2];
        int cls = 0; float best = v0;
        if (v1 > best) { best = v1; cls = 1; }
        if (v2 > best) { cls = 2; }
        g_maskS[warp] = (float)(cls - 1);
    }
}

__global__ void sum_kernel() {
    float sf = 0.f, ss = 0.f;
    for (int i = blockIdx.x * blockDim.x + threadIdx.x; i < E; i += gridDim.x * blockDim.x) {
        sf += fabsf(g_maskF[i]);
        ss += fabsf(g_maskS[i]);
    }
#pragma unroll
    for (int off = 16; off; off >>= 1) {
        sf += __shfl_xor_sync(0xffffffffu, sf, off);
        ss += __shfl_xor_sync(0xffffffffu, ss, off);
    }
    __shared__ float shf[8], shs[8];
    int w = threadIdx.x >> 5, l = threadIdx.x & 31;
    if (l == 0) { shf[w] = sf; shs[w] = ss; }
    __syncthreads();
    if (threadIdx.x == 0) {
        float a = 0.f, b = 0.f;
        for (int i = 0; i < 8; i++) { a += shf[i]; b += shs[i]; }
        atomicAdd(&g_sums[0], a);
        atomicAdd(&g_sums[1], b);
    }
}

__global__ void wedge_kernel(const int* __restrict__ e0, const float* __restrict__ fw) {
    int i = blockIdx.x * blockDim.x + threadIdx.x;
    if (i >= E) return;
    float w0 = fw[0], w1 = fw[1], w2 = fw[2];
    float m = fmaxf(w0, fmaxf(w1, w2));
    float ex0 = expf(w0 - m), ex1 = expf(w1 - m), ex2 = expf(w2 - m);
    float s = ex0 + ex1 + ex2;
    float sw0 = ex0 / s, sw1 = ex1 / s, sw2 = ex2 / s;
    float nO = 1.f / (float)E;
    float nF = g_maskF[i] / fmaxf(g_sums[0], 1e-12f);
    float nS = g_maskS[i] / fmaxf(g_sums[1], 1e-12f);
    float fused = sw0 * nO + sw1 * nF + sw2 * nS;
    float w = (fused > 0.5f) ? 1.f : 0.f;
    g_we[i] = w;
    if (w != 0.f) atomicAdd(&g_deg[e0[i]], w);
}

__global__ void dis_kernel() {
    int i = blockIdx.x * blockDim.x + threadIdx.x;
    if (i < NN) {
        float d = g_deg[i];
        g_deg[i] = (d > 0.f) ? rsqrtf(fmaxf(d, 1e-12f)) : 0.f;
    }
}

__global__ void norm_kernel(const int* __restrict__ e0, const int* __restrict__ e1) {
    int i = blockIdx.x * blockDim.x + threadIdx.x;
    if (i >= E) return;
    g_norm[i] = g_deg[e0[i]] * g_we[i] * g_deg[e1[i]];
}

__global__ void initacc_kernel(const float* __restrict__ lgu, const float* __restrict__ lgi) {
    int i = blockIdx.x * blockDim.x + threadIdx.x;
    if (i >= NN * D) return;
    float v = (i < NU * D) ? lgu[i] : lgi[i - NU * D];
    g_acc[i] = v;
    g_xk[i]  = v;
    g_xk2[i] = 0.f;
}

__device__ __forceinline__ void red_add_v4(float* p, float x, float y, float z, float w) {
    asm volatile("red.global.add.v4.f32 [%0], {%1,%2,%3,%4};"
                 :: "l"(p), "f"(x), "f"(y), "f"(z), "f"(w) : "memory");
}

__global__ void prop_kernel(const int* __restrict__ e0, const int* __restrict__ e1,
                            const float* __restrict__ xin, float* __restrict__ xout) {
    int t = blockIdx.x * blockDim.x + threadIdx.x;
    int e = t >> 4;
    if (e >= E) return;
    float nm = g_norm[e];
    if (nm == 0.f) return;
    int c = (t & 15) * 4;
    int s = e1[e], d = e0[e];
    float4 v = *(const float4*)&xin[s * D + c];
    red_add_v4(&xout[d * D + c], nm * v.x, nm * v.y, nm * v.z, nm * v.w);
}

// acc += xnew; zero the now-dead buffer for next iteration
__global__ void accadd_zero(const float* __restrict__ xnew, float* __restrict__ xold) {
    int i = blockIdx.x * blockDim.x + threadIdx.x;
    if (i < NN * D) { g_acc[i] += xnew[i]; xold[i] = 0.f; }
}

__global__ void out_kernel(const float* __restrict__ lgu, const float* __restrict__ lgi,
                           float* __restrict__ out, int n) {
    int i = blockIdx.x * blockDim.x + threadIdx.x;
    if (i >= n) return;
    constexpr int A = NU * D;
    constexpr int C = NF * D;
    if (i < A)               out[i] = g_acc[i] * 0.25f;
    else if (i < 2 * A)      out[i] = lgu[i - A];
    else if (i < 2 * A + C)  out[i] = g_acc[A + (i - 2 * A)] * 0.25f;
    else                     out[i] = lgi[i - 2 * A - C];
}

// ---------------- launch ----------------
extern "C" void kernel_launch(void* const* d_in, const int* in_sizes, int n_in,
                              void* d_out, int out_size) {
    const float* user_feat = (const float*)d_in[0];
    const float* food_feat = (const float*)d_in[1];
    const int*   ei        = (const int*)d_in[2];
    const int*   pe        = (const int*)d_in[3];
    const int*   ne        = (const int*)d_in[4];
    const float* W_user    = (const float*)d_in[5];
    const float* b_user    = (const float*)d_in[6];
    const float* W_food    = (const float*)d_in[7];
    const float* b_food    = (const float*)d_in[8];
    const float* metric_w  = (const float*)d_in[9];
    const float* fusion_w  = (const float*)d_in[10];
    const float* sg_u      = (const float*)d_in[11];
    const float* sg_i      = (const float*)d_in[12];
    const float* c1_pl     = (const float*)d_in[13];
    const float* c1_prw    = (const float*)d_in[14];
    const float* c1_prb    = (const float*)d_in[15];
    const float* c1_nl     = (const float*)d_in[16];
    const float* c1_nrw    = (const float*)d_in[17];
    const float* c1_nrb    = (const float*)d_in[18];
    const float* cs_pl     = (const float*)d_in[19];
    const float* cs_prw    = (const float*)d_in[20];
    const float* cs_prb    = (const float*)d_in[21];
    const float* cs_nl     = (const float*)d_in[22];
    const float* cs_nrw    = (const float*)d_in[23];
    const float* cs_nrb    = (const float*)d_in[24];
    const float* lin_w     = (const float*)d_in[25];
    const float* lin_b     = (const float*)d_in[26];
    const float* lg_u      = (const float*)d_in[27];
    const float* lg_i      = (const float*)d_in[28];
    float* out = (float*)d_out;

    void *a_u, *a_f, *a_x, *a_y, *a_cnt2, *a_fill2, *a_deg, *a_sums,
         *a_xk, *a_xk2, *a_nau, *a_naf;
    cudaGetSymbolAddress(&a_u, g_u);
    cudaGetSymbolAddress(&a_f, g_f);
    cudaGetSymbolAddress(&a_x, g_x);
    cudaGetSymbolAddress(&a_y, g_y);
    cudaGetSymbolAddress(&a_cnt2, g_cnt2);
    cudaGetSymbolAddress(&a_fill2, g_fill2);
    cudaGetSymbolAddress(&a_deg, g_deg);
    cudaGetSymbolAddress(&a_sums, g_sums);
    cudaGetSymbolAddress(&a_xk, g_xk);
    cudaGetSymbolAddress(&a_xk2, g_xk2);
    cudaGetSymbolAddress(&a_nau, g_nau);
    cudaGetSymbolAddress(&a_naf, g_naf);

    const int TPB = 256;
    const int gE     = (E + TPB - 1) / TPB;
    const int gEw    = (E * 32 + TPB - 1) / TPB;
    const int gE16   = (E * 16 + TPB - 1) / TPB;
    const int gBE    = (EP + EN + TPB - 1) / TPB;
    const int gN     = (NN + TPB - 1) / TPB;
    const int gND    = (NN * D + TPB - 1) / TPB;
    const int gNode8 = (NN + 7) / 8;
    const int nScanBlocks = (2 * NN + 1023) / 1024;

    // 1. feature GEMMs (tiled)
    gemm_relu_t<<<(NU + 63) / 64, TPB>>>(user_feat, W_user, b_user, (float*)a_u, NU);
    gemm_relu_t<<<(NF + 63) / 64, TPB>>>(food_feat, W_food, b_food, (float*)a_f, NF);

    // 2. per-node norms, then per-edge similarity -> mask_feature
    node_norms<<<(NU * 32 + TPB - 1) / TPB, TPB>>>((const float*)a_u, metric_w, (float4*)a_nau, NU);
    node_norms<<<(NF * 32 + TPB - 1) / TPB, TPB>>>((const float*)a_f, metric_w, (float4*)a_naf, NF);
    sim_kernel<<<gEw, TPB>>>(ei, ei + E, metric_w);

    // 3. CSR build for pos/neg edge sets
    cudaMemsetAsync(a_cnt2, 0, 2 * NN * sizeof(int));
    cudaMemsetAsync(a_fill2, 0, 2 * NN * sizeof(int));
    hist_kernel<<<gBE, TPB>>>(pe + EP, ne + EN);
    scan1_kernel<<<nScanBlocks, 1024>>>();
    scan2_kernel<<<1, 256>>>(nScanBlocks);
    scan3_kernel<<<(2 * NN + TPB - 1) / TPB, TPB>>>();
    fill_csr<<<gBE, TPB>>>(pe, ne);

    // 4. signed conv: fused gather+mean+transform, 3 layers
    copyx_kernel<<<gND, TPB>>>(sg_u, sg_i);
    conv1_fused<<<gNode8, TPB>>>(c1_pl, c1_prw, c1_prb, c1_nl, c1_nrw, c1_nrb);           // x -> y
    conv2_fused<<<gNode8, TPB>>>(cs_pl, cs_prw, cs_prb, cs_nl, cs_nrw, cs_nrb,
                                 (const float*)a_y, (float*)a_x);                          // y -> x
    conv2_fused<<<gNode8, TPB>>>(cs_pl + D * H2, cs_prw + H2 * H2, cs_prb + H2,
                                 cs_nl + D * H2, cs_nrw + H2 * H2, cs_nrb + H2,
                                 (const float*)a_x, (float*)a_y);                          // x -> y

    // 5. per-edge classifier -> mask_semantic
    class_kernel<<<gEw, TPB>>>(ei, ei + E, (const float*)a_y, lin_w, lin_b);

    // 6. mask L1 sums, fused mask, degrees, norm
    cudaMemsetAsync(a_sums, 0, 2 * sizeof(float));
    sum_kernel<<<256, TPB>>>();
    cudaMemsetAsync(a_deg, 0, NN * sizeof(float));
    wedge_kernel<<<gE, TPB>>>(ei, fusion_w);
    dis_kernel<<<gN, TPB>>>();
    norm_kernel<<<gE, TPB>>>(ei, ei + E);

    // 7. LightGCN propagation (3 hops); initacc zeros xk2
    initacc_kernel<<<gND, TPB>>>(lg_u, lg_i);
    float* cur = (float*)a_xk;
    float* nxt = (float*)a_xk2;
    for (int it = 0; it < 3; it++) {
        prop_kernel<<<gE16, TPB>>>(ei, ei + E, cur, nxt);
        accadd_zero<<<gND, TPB>>>(nxt, cur);   // acc += nxt; zero cur for reuse as next nxt
        float* t = cur; cur = nxt; nxt = t;
    }

    // 8. outputs
    out_kernel<<<(out_size + TPB - 1) / TPB, TPB>>>(lg_u, lg_i, out, out_size);
}

// round 5
// speedup vs baseline: 1.7845x; 1.0797x over previous
#include <cuda_runtime.h>
#include <math.h>

// ---------------- problem constants ----------------
constexpr int NU = 50000, NF = 50000, NN = 100000;
constexpr int D  = 64,    H2 = 32,    FU = 256;
constexpr int E  = 500000, EP = 500000, EN = 500000;
constexpr int NH = 4;
constexpr float THRESH = 0.3f;

// ---------------- device scratch (no allocs allowed) ----------------
__device__ float g_u[NU * D];
__device__ float g_f[NF * D];
__device__ float g_x[NN * D];      // conv pong
__device__ float g_y[NN * D];      // conv ping
__device__ float g_maskF[E];
__device__ float g_maskS[E];
__device__ float g_we[E];
__device__ float g_norm[E];
__device__ float g_deg[NN];        // becomes dis
__device__ float g_xk[NN * D];
__device__ float g_xk2[NN * D];
__device__ float g_acc[NN * D];
__device__ float g_sums[2];
__device__ float4 g_nau[NU];
__device__ float4 g_naf[NF];
// CSR scratch
__device__ int g_cnt2[2 * NN];
__device__ int g_ptr2[2 * NN];
__device__ int g_fill2[2 * NN];
__device__ int g_bsum[256];
__device__ int g_csrP[EP];
__device__ int g_csrN[EN];

// ---------------- GEMM: both matrices, 128x64 tile, 8x4 per thread ----------------
__global__ void gemm2(const float* __restrict__ fu, const float* __restrict__ Wu,
                      const float* __restrict__ bu,
                      const float* __restrict__ ff, const float* __restrict__ Wf,
                      const float* __restrict__ bf) {
    constexpr int NBU = (NU + 127) / 128;
    bool isU = blockIdx.x < NBU;
    const float* feat = isU ? fu : ff;
    const float* W    = isU ? Wu : Wf;
    const float* bias = isU ? bu : bf;
    float* out        = isU ? g_u : g_f;
    int rows          = isU ? NU : NF;
    int bx            = isU ? blockIdx.x : blockIdx.x - NBU;

    __shared__ float sA[32][132];   // sA[k][r]
    __shared__ float sB[32][64];    // sB[k][c]
    int tid = threadIdx.x;
    int tx = tid & 15, ty = tid >> 4;   // tx: col/4 (0..15), ty: row/8 (0..15)
    int row0 = bx * 128;
    float acc[8][4];
#pragma unroll
    for (int i = 0; i < 8; i++)
#pragma unroll
        for (int j = 0; j < 4; j++) acc[i][j] = 0.f;

    for (int k0 = 0; k0 < FU; k0 += 32) {
        int r = tid >> 1;
        int kk = (tid & 1) * 16;
        int grow = row0 + r;
        float4 v[4];
        if (grow < rows) {
            const float4* s = (const float4*)&feat[grow * FU + k0 + kk];
            v[0] = s[0]; v[1] = s[1]; v[2] = s[2]; v[3] = s[3];
        } else {
            v[0] = make_float4(0.f, 0.f, 0.f, 0.f); v[1] = v[0]; v[2] = v[0]; v[3] = v[0];
        }
#pragma unroll
        for (int q = 0; q < 4; q++) {
            sA[kk + q * 4 + 0][r] = v[q].x; sA[kk + q * 4 + 1][r] = v[q].y;
            sA[kk + q * 4 + 2][r] = v[q].z; sA[kk + q * 4 + 3][r] = v[q].w;
        }
        {
            int idx = tid * 8, kw = idx >> 6, cw = idx & 63;
            const float4* ws = (const float4*)&W[(k0 + kw) * D + cw];
            *(float4*)&sB[kw][cw]     = ws[0];
            *(float4*)&sB[kw][cw + 4] = ws[1];
        }
        __syncthreads();
#pragma unroll
        for (int k = 0; k < 32; k++) {
            float4 b  = *(float4*)&sB[k][tx * 4];
            float4 a0 = *(float4*)&sA[k][ty * 8];
            float4 a1 = *(float4*)&sA[k][ty * 8 + 4];
            acc[0][0] += a0.x * b.x; acc[0][1] += a0.x * b.y; acc[0][2] += a0.x * b.z; acc[0][3] += a0.x * b.w;
            acc[1][0] += a0.y * b.x; acc[1][1] += a0.y * b.y; acc[1][2] += a0.y * b.z; acc[1][3] += a0.y * b.w;
            acc[2][0] += a0.z * b.x; acc[2][1] += a0.z * b.y; acc[2][2] += a0.z * b.z; acc[2][3] += a0.z * b.w;
            acc[3][0] += a0.w * b.x; acc[3][1] += a0.w * b.y; acc[3][2] += a0.w * b.z; acc[3][3] += a0.w * b.w;
            acc[4][0] += a1.x * b.x; acc[4][1] += a1.x * b.y; acc[4][2] += a1.x * b.z; acc[4][3] += a1.x * b.w;
            acc[5][0] += a1.y * b.x; acc[5][1] += a1.y * b.y; acc[5][2] += a1.y * b.z; acc[5][3] += a1.y * b.w;
            acc[6][0] += a1.z * b.x; acc[6][1] += a1.z * b.y; acc[6][2] += a1.z * b.z; acc[6][3] += a1.z * b.w;
            acc[7][0] += a1.w * b.x; acc[7][1] += a1.w * b.y; acc[7][2] += a1.w * b.z; acc[7][3] += a1.w * b.w;
        }
        __syncthreads();
    }
    float4 bb = *(const float4*)&bias[tx * 4];
#pragma unroll
    for (int i = 0; i < 8; i++) {
        int grow = row0 + ty * 8 + i;
        if (grow < rows) {
            float4 o;
            o.x = fmaxf(acc[i][0] + bb.x, 0.f);
            o.y = fmaxf(acc[i][1] + bb.y, 0.f);
            o.z = fmaxf(acc[i][2] + bb.z, 0.f);
            o.w = fmaxf(acc[i][3] + bb.w, 0.f);
            *(float4*)&out[grow * D + tx * 4] = o;
        }
    }
}

// ---------------- per-node per-head norms (both node sets) ----------------
__global__ void node_norms2(const float* __restrict__ mw) {
    __shared__ float smw[NH * D];
    if (threadIdx.x < NH * D) smw[threadIdx.x] = mw[threadIdx.x];
    __syncthreads();
    int warp = (blockIdx.x * blockDim.x + threadIdx.x) >> 5;
    int lane = threadIdx.x & 31;
    if (warp >= NU + NF) return;
    const float* x; float4* o;
    if (warp < NU) { x = &g_u[warp * D]; o = &g_nau[warp]; }
    else           { x = &g_f[(warp - NU) * D]; o = &g_naf[warp - NU]; }
    float x0 = x[lane], x1 = x[32 + lane];
    float s[NH];
#pragma unroll
    for (int h = 0; h < NH; h++) {
        float a0 = x0 * smw[h * D + lane];
        float a1 = x1 * smw[h * D + 32 + lane];
        s[h] = a0 * a0 + a1 * a1;
    }
#pragma unroll
    for (int off = 16; off; off >>= 1)
#pragma unroll
        for (int h = 0; h < NH; h++) s[h] += __shfl_xor_sync(0xffffffffu, s[h], off);
    if (lane == 0)
        *o = make_float4(fmaxf(sqrtf(s[0]), 1e-8f), fmaxf(sqrtf(s[1]), 1e-8f),
                         fmaxf(sqrtf(s[2]), 1e-8f), fmaxf(sqrtf(s[3]), 1e-8f));
}

// per-edge multi-head cosine similarity -> mask_feature
__global__ void sim_kernel(const int* __restrict__ e0, const int* __restrict__ e1,
                           const float* __restrict__ mw) {
    __shared__ float smw2[NH * D];
    if (threadIdx.x < NH * D) { float w = mw[threadIdx.x]; smw2[threadIdx.x] = w * w; }
    __syncthreads();
    int warp = (blockIdx.x * blockDim.x + threadIdx.x) >> 5;
    int lane = threadIdx.x & 31;
    if (warp >= E) return;
    int a = e0[warp], b = e1[warp];
    float u0 = g_u[a * D + lane],  u1 = g_u[a * D + 32 + lane];
    float f0 = g_f[b * D + lane],  f1 = g_f[b * D + 32 + lane];
    float p0 = u0 * f0, p1 = u1 * f1;
    float d[NH];
#pragma unroll
    for (int h = 0; h < NH; h++)
        d[h] = p0 * smw2[h * D + lane] + p1 * smw2[h * D + 32 + lane];
#pragma unroll
    for (int off = 16; off; off >>= 1)
#pragma unroll
        for (int h = 0; h < NH; h++) d[h] += __shfl_xor_sync(0xffffffffu, d[h], off);
    if (lane == 0) {
        float4 na = g_nau[a], nb = g_naf[b];
        float sim = d[0] / (na.x * nb.x) + d[1] / (na.y * nb.y)
                  + d[2] / (na.z * nb.z) + d[3] / (na.w * nb.w);
        sim *= (1.f / NH);
        g_maskF[warp] = (sim < THRESH) ? 0.f : sim;
    }
}

// ---------------- CSR build ----------------
__global__ void hist_kernel(const int* __restrict__ pd, const int* __restrict__ nd) {
    int i = blockIdx.x * blockDim.x + threadIdx.x;
    if (i < EP) atomicAdd(&g_cnt2[pd[i]], 1);
    else {
        i -= EP;
        if (i < EN) atomicAdd(&g_cnt2[NN + nd[i]], 1);
    }
}

__global__ void scan1_kernel() {
    __shared__ int sh[1024];
    int i = blockIdx.x * 1024 + threadIdx.x;
    int v = (i < 2 * NN) ? g_cnt2[i] : 0;
    sh[threadIdx.x] = v;
    __syncthreads();
    for (int off = 1; off < 1024; off <<= 1) {
        int t = (threadIdx.x >= off) ? sh[threadIdx.x - off] : 0;
        __syncthreads();
        sh[threadIdx.x] += t;
        __syncthreads();
    }
    if (i < 2 * NN) g_ptr2[i] = sh[threadIdx.x] - v;
    if (threadIdx.x == 1023) g_bsum[blockIdx.x] = sh[1023];
}

__global__ void scan2_kernel(int nb) {
    __shared__ int sh[256];
    int v = (threadIdx.x < nb) ? g_bsum[threadIdx.x] : 0;
    sh[threadIdx.x] = v;
    __syncthreads();
    for (int off = 1; off < 256; off <<= 1) {
        int t = (threadIdx.x >= off) ? sh[threadIdx.x - off] : 0;
        __syncthreads();
        sh[threadIdx.x] += t;
        __syncthreads();
    }
    if (threadIdx.x < nb) g_bsum[threadIdx.x] = sh[threadIdx.x] - v;
}

__global__ void scan3_kernel() {
    int i = blockIdx.x * blockDim.x + threadIdx.x;
    if (i < 2 * NN) g_ptr2[i] += g_bsum[i >> 10];
}

__global__ void fill_csr(const int* __restrict__ pe, const int* __restrict__ ne) {
    int i = blockIdx.x * blockDim.x + threadIdx.x;
    if (i < EP) {
        int d = pe[EP + i];
        int slot = atomicAdd(&g_fill2[d], 1);
        g_csrP[g_ptr2[d] + slot] = pe[i];
    } else {
        i -= EP;
        if (i < EN) {
            int d = ne[EN + i];
            int slot = atomicAdd(&g_fill2[NN + d], 1);
            g_csrN[(g_ptr2[NN + d] - EP) + slot] = ne[i];
        }
    }
}

// select-load from the two sg embedding inputs (conv1 input, avoids copyx)
__device__ __forceinline__ float ld_sg(const float* __restrict__ sgu,
                                       const float* __restrict__ sgi, int s, int c) {
    return (s < NU) ? sgu[s * D + c] : sgi[(s - NU) * D + c];
}

// ---------------- fused conv layer 1 ----------------
__global__ void conv1_fused(const float* __restrict__ sgu, const float* __restrict__ sgi,
                            const float* __restrict__ pl, const float* __restrict__ prw,
                            const float* __restrict__ prb,
                            const float* __restrict__ nl, const float* __restrict__ nrw,
                            const float* __restrict__ nrb) {
    __shared__ float s_pl[D * H2], s_prw[D * H2], s_nl[D * H2], s_nrw[D * H2];
    __shared__ float stage[8 * 192];
    for (int i = threadIdx.x; i < D * H2; i += 256) {
        s_pl[i] = pl[i]; s_prw[i] = prw[i]; s_nl[i] = nl[i]; s_nrw[i] = nrw[i];
    }
    __syncthreads();
    int w = threadIdx.x >> 5, c = threadIdx.x & 31;
    int node = blockIdx.x * 8 + w;
    if (node >= NN) return;
    int p0 = g_ptr2[node], p1 = g_ptr2[node + 1];
    int n0 = g_ptr2[NN + node] - EP;
    int n1 = ((node == NN - 1) ? EN : (g_ptr2[NN + node + 1] - EP));
    float mp0 = 0.f, mp1 = 0.f, mn0 = 0.f, mn1 = 0.f;
    for (int j = p0; j < p1; j++) {
        int s = g_csrP[j];
        mp0 += ld_sg(sgu, sgi, s, c); mp1 += ld_sg(sgu, sgi, s, 32 + c);
    }
    for (int j = n0; j < n1; j++) {
        int s = g_csrN[j];
        mn0 += ld_sg(sgu, sgi, s, c); mn1 += ld_sg(sgu, sgi, s, 32 + c);
    }
    float invP = 1.f / fmaxf((float)(p1 - p0), 1.f);
    float invN = 1.f / fmaxf((float)(n1 - n0), 1.f);
    float* st = &stage[w * 192];
    st[c]       = mp0 * invP; st[32 + c]  = mp1 * invP;
    st[64 + c]  = mn0 * invN; st[96 + c]  = mn1 * invN;
    st[128 + c] = ld_sg(sgu, sgi, node, c);
    st[160 + c] = ld_sg(sgu, sgi, node, 32 + c);
    __syncwarp();
    float accP = prb[c], accN = nrb[c];
#pragma unroll 8
    for (int k = 0; k < D; k++) {
        float mpk = st[k], mnk = st[64 + k], xk = st[128 + k];
        accP += mpk * s_pl[k * H2 + c] + xk * s_prw[k * H2 + c];
        accN += mnk * s_nl[k * H2 + c] + xk * s_nrw[k * H2 + c];
    }
    g_y[node * D + c]      = fmaxf(accP, 0.f);
    g_y[node * D + 32 + c] = fmaxf(accN, 0.f);
}

// ---------------- fused conv layers 2/3 ----------------
__global__ void conv2_fused(const float* __restrict__ pl, const float* __restrict__ prw,
                            const float* __restrict__ prb,
                            const float* __restrict__ nl, const float* __restrict__ nrw,
                            const float* __restrict__ nrb,
                            const float* __restrict__ zin, float* __restrict__ zout) {
    __shared__ float s_pl[D * H2], s_nl[D * H2], s_prw[H2 * H2], s_nrw[H2 * H2];
    __shared__ float stage[8 * 192];
    for (int i = threadIdx.x; i < D * H2; i += 256) { s_pl[i] = pl[i]; s_nl[i] = nl[i]; }
    for (int i = threadIdx.x; i < H2 * H2; i += 256) { s_prw[i] = prw[i]; s_nrw[i] = nrw[i]; }
    __syncthreads();
    int w = threadIdx.x >> 5, c = threadIdx.x & 31;
    int node = blockIdx.x * 8 + w;
    if (node >= NN) return;
    int p0 = g_ptr2[node], p1 = g_ptr2[node + 1];
    int n0 = g_ptr2[NN + node] - EP;
    int n1 = ((node == NN - 1) ? EN : (g_ptr2[NN + node + 1] - EP));
    float pp = 0.f, pn = 0.f, np_ = 0.f, nn = 0.f;
    for (int j = p0; j < p1; j++) {
        int s = g_csrP[j];
        pp += zin[s * D + c]; pn += zin[s * D + 32 + c];
    }
    for (int j = n0; j < n1; j++) {
        int s = g_csrN[j];
        np_ += zin[s * D + c]; nn += zin[s * D + 32 + c];
    }
    float invP = 1.f / fmaxf((float)(p1 - p0), 1.f);
    float invN = 1.f / fmaxf((float)(n1 - n0), 1.f);
    float* st = &stage[w * 192];
    st[c]       = pp * invP;  st[32 + c] = nn * invN;
    st[64 + c]  = pn * invP;  st[96 + c] = np_ * invN;
    st[128 + c] = zin[node * D + c];
    st[160 + c] = zin[node * D + 32 + c];
    __syncwarp();
    float accP = prb[c], accN = nrb[c];
#pragma unroll 8
    for (int k = 0; k < D; k++) {
        accP += st[k]      * s_pl[k * H2 + c];
        accN += st[64 + k] * s_nl[k * H2 + c];
    }
#pragma unroll 8
    for (int k = 0; k < H2; k++) {
        accP += st[128 + k] * s_prw[k * H2 + c];
        accN += st[160 + k] * s_nrw[k * H2 + c];
    }
    zout[node * D + c]      = fmaxf(accP, 0.f);
    zout[node * D + 32 + c] = fmaxf(accN, 0.f);
}

// ---------------- per-edge classifier ----------------
__global__ void class_kernel(const int* __restrict__ e0, const int* __restrict__ e1,
                             const float* __restrict__ z,
                             const float* __restrict__ lw, const float* __restrict__ lb) {
    __shared__ float slw[2 * D * 3];
    __shared__ float slb[3];
    for (int i = threadIdx.x; i < 2 * D * 3; i += 256) slw[i] = lw[i];
    if (threadIdx.x < 3) slb[threadIdx.x] = lb[threadIdx.x];
    __syncthreads();
    int warp = (blockIdx.x * blockDim.x + threadIdx.x) >> 5;
    int lane = threadIdx.x & 31;
    if (warp >= E) return;
    int a = e0[warp], b = e1[warp];
    float za0 = z[a * D + lane], za1 = z[a * D + 32 + lane];
    float zb0 = z[b * D + lane], zb1 = z[b * D + 32 + lane];
    float v0 = za0 * slw[lane * 3 + 0] + za1 * slw[(32 + lane) * 3 + 0]
             + zb0 * slw[(64 + lane) * 3 + 0] + zb1 * slw[(96 + lane) * 3 + 0];
    float v1 = za0 * slw[lane * 3 + 1] + za1 * slw[(32 + lane) * 3 + 1]
             + zb0 * slw[(64 + lane) * 3 + 1] + zb1 * slw[(96 + lane) * 3 + 1];
    float v2 = za0 * slw[lane * 3 + 2] + za1 * slw[(32 + lane) * 3 + 2]
             + zb0 * slw[(64 + lane) * 3 + 2] + zb1 * slw[(96 + lane) * 3 + 2];
#pragma unroll
    for (int off = 16; off; off >>= 1) {
        v0 += __shfl_xor_sync(0xffffffffu, v0, off);
        v1 += __shfl_xor_sync(0xffffffffu, v1, off);
        v2 += __shfl_xor_sync(0xffffffffu, v2, off);
    }
    if (lane == 0) {
        v0 += slb[0]; v1 += slb[1]; v2 += slb[2];
        int cls = 0; float best = v0;
        if (v1 > best) { best = v1; cls = 1; }
        if (v2 > best) { cls = 2; }
        g_maskS[warp] = (float)(cls - 1);
    }
}

// ---------------- mask fusion path ----------------
__global__ void sum_kernel() {
    float sf = 0.f, ss = 0.f;
    for (int i = blockIdx.x * blockDim.x + threadIdx.x; i < E; i += gridDim.x * blockDim.x) {
        sf += fabsf(g_maskF[i]);
        ss += fabsf(g_maskS[i]);
    }
#pragma unroll
    for (int off = 16; off; off >>= 1) {
        sf += __shfl_xor_sync(0xffffffffu, sf, off);
        ss += __shfl_xor_sync(0xffffffffu, ss, off);
    }
    __shared__ float shf[8], shs[8];
    int w = threadIdx.x >> 5, l = threadIdx.x & 31;
    if (l == 0) { shf[w] = sf; shs[w] = ss; }
    __syncthreads();
    if (threadIdx.x == 0) {
        float a = 0.f, b = 0.f;
        for (int i = 0; i < 8; i++) { a += shf[i]; b += shs[i]; }
        atomicAdd(&g_sums[0], a);
        atomicAdd(&g_sums[1], b);
    }
}

__global__ void wedge_kernel(const int* __restrict__ e0, const float* __restrict__ fw) {
    int i = blockIdx.x * blockDim.x + threadIdx.x;
    if (i >= E) return;
    float w0 = fw[0], w1 = fw[1], w2 = fw[2];
    float m = fmaxf(w0, fmaxf(w1, w2));
    float ex0 = expf(w0 - m), ex1 = expf(w1 - m), ex2 = expf(w2 - m);
    float s = ex0 + ex1 + ex2;
    float sw0 = ex0 / s, sw1 = ex1 / s, sw2 = ex2 / s;
    float nO = 1.f / (float)E;
    float nF = g_maskF[i] / fmaxf(g_sums[0], 1e-12f);
    float nS = g_maskS[i] / fmaxf(g_sums[1], 1e-12f);
    float fused = sw0 * nO + sw1 * nF + sw2 * nS;
    float w = (fused > 0.5f) ? 1.f : 0.f;
    g_we[i] = w;
    if (w != 0.f) atomicAdd(&g_deg[e0[i]], w);
}

__global__ void dis_kernel() {
    int i = blockIdx.x * blockDim.x + threadIdx.x;
    if (i < NN) {
        float d = g_deg[i];
        g_deg[i] = (d > 0.f) ? rsqrtf(fmaxf(d, 1e-12f)) : 0.f;
    }
}

__global__ void norm_kernel(const int* __restrict__ e0, const int* __restrict__ e1) {
    int i = blockIdx.x * blockDim.x + threadIdx.x;
    if (i >= E) return;
    g_norm[i] = g_deg[e0[i]] * g_we[i] * g_deg[e1[i]];
}

// ---------------- LightGCN ----------------
__global__ void initacc_kernel(const float* __restrict__ lgu, const float* __restrict__ lgi) {
    int i = blockIdx.x * blockDim.x + threadIdx.x;
    if (i >= NN * D) return;
    float v = (i < NU * D) ? lgu[i] : lgi[i - NU * D];
    g_acc[i] = v;
    g_xk[i]  = v;
    g_xk2[i] = 0.f;
}

__device__ __forceinline__ void red_add_v4(float* p, float x, float y, float z, float w) {
    asm volatile("red.global.add.v4.f32 [%0], {%1,%2,%3,%4};"
                 :: "l"(p), "f"(x), "f"(y), "f"(z), "f"(w) : "memory");
}

__global__ void prop_kernel(const int* __restrict__ e0, const int* __restrict__ e1,
                            const float* __restrict__ xin, float* __restrict__ xout) {
    int t = blockIdx.x * blockDim.x + threadIdx.x;
    int e = t >> 4;
    if (e >= E) return;
    float nm = g_norm[e];
    if (nm == 0.f) return;
    int c = (t & 15) * 4;
    int s = e1[e], d = e0[e];
    float4 v = *(const float4*)&xin[s * D + c];
    red_add_v4(&xout[d * D + c], nm * v.x, nm * v.y, nm * v.z, nm * v.w);
}

__global__ void accadd_zero(const float* __restrict__ xnew, float* __restrict__ xold) {
    int i = blockIdx.x * blockDim.x + threadIdx.x;
    if (i < NN * D) { g_acc[i] += xnew[i]; xold[i] = 0.f; }
}

// final hop fused with output: out_users/out_foods = (acc + x3)/4
__global__ void out_final(const float* __restrict__ x3, float* __restrict__ out) {
    int i = blockIdx.x * blockDim.x + threadIdx.x;
    if (i >= NN * D) return;
    constexpr int A = NU * D;
    float v = (g_acc[i] + x3[i]) * 0.25f;
    if (i < A) out[i]     = v;    // final_u
    else       out[A + i] = v;    // final_f at [2A : 2A+C)
}

// lg embedding copies into out (independent of everything, runs early)
__global__ void out_copy(const float* __restrict__ lgu, const float* __restrict__ lgi,
                         float* __restrict__ out) {
    int i = blockIdx.x * blockDim.x + threadIdx.x;
    if (i >= NN * D) return;
    constexpr int A = NU * D;
    if (i < A) out[A + i]     = lgu[i];       // lg_u at [A : 2A)
    else       out[2 * A + i] = lgi[i - A];   // lg_i at [3A : 4A)
}

// ---------------- launch ----------------
extern "C" void kernel_launch(void* const* d_in, const int* in_sizes, int n_in,
                              void* d_out, int out_size) {
    const float* user_feat = (const float*)d_in[0];
    const float* food_feat = (const float*)d_in[1];
    const int*   ei        = (const int*)d_in[2];
    const int*   pe        = (const int*)d_in[3];
    const int*   ne        = (const int*)d_in[4];
    const float* W_user    = (const float*)d_in[5];
    const float* b_user    = (const float*)d_in[6];
    const float* W_food    = (const float*)d_in[7];
    const float* b_food    = (const float*)d_in[8];
    const float* metric_w  = (const float*)d_in[9];
    const float* fusion_w  = (const float*)d_in[10];
    const float* sg_u      = (const float*)d_in[11];
    const float* sg_i      = (const float*)d_in[12];
    const float* c1_pl     = (const float*)d_in[13];
    const float* c1_prw    = (const float*)d_in[14];
    const float* c1_prb    = (const float*)d_in[15];
    const float* c1_nl     = (const float*)d_in[16];
    const float* c1_nrw    = (const float*)d_in[17];
    const float* c1_nrb    = (const float*)d_in[18];
    const float* cs_pl     = (const float*)d_in[19];
    const float* cs_prw    = (const float*)d_in[20];
    const float* cs_prb    = (const float*)d_in[21];
    const float* cs_nl     = (const float*)d_in[22];
    const float* cs_nrw    = (const float*)d_in[23];
    const float* cs_nrb    = (const float*)d_in[24];
    const float* lin_w     = (const float*)d_in[25];
    const float* lin_b     = (const float*)d_in[26];
    const float* lg_u      = (const float*)d_in[27];
    const float* lg_i      = (const float*)d_in[28];
    float* out = (float*)d_out;

    void *a_x, *a_y, *a_cnt2, *a_fill2, *a_deg, *a_sums, *a_xk, *a_xk2;
    cudaGetSymbolAddress(&a_x, g_x);
    cudaGetSymbolAddress(&a_y, g_y);
    cudaGetSymbolAddress(&a_cnt2, g_cnt2);
    cudaGetSymbolAddress(&a_fill2, g_fill2);
    cudaGetSymbolAddress(&a_deg, g_deg);
    cudaGetSymbolAddress(&a_sums, g_sums);
    cudaGetSymbolAddress(&a_xk, g_xk);
    cudaGetSymbolAddress(&a_xk2, g_xk2);

    // Persistent side streams + events for fork/join inside graph capture.
    // Created once on the first (eager) call; used identically every call, so
    // the launched work is deterministic. If creation fails they remain 0 and
    // all launches fall back to the origin stream in dependency-correct order.
    static cudaStream_t sB = 0, sC = 0;
    static cudaEvent_t evR = 0, evB = 0, evC = 0;
    static bool s_init = false;
    if (!s_init) {
        cudaStreamCreateWithFlags(&sB, cudaStreamNonBlocking);
        cudaStreamCreateWithFlags(&sC, cudaStreamNonBlocking);
        cudaEventCreateWithFlags(&evR, cudaEventDisableTiming);
        cudaEventCreateWithFlags(&evB, cudaEventDisableTiming);
        cudaEventCreateWithFlags(&evC, cudaEventDisableTiming);
        s_init = true;
    }

    const int TPB = 256;
    const int gE     = (E + TPB - 1) / TPB;
    const int gEw    = (E * 32 + TPB - 1) / TPB;
    const int gE16   = (E * 16 + TPB - 1) / TPB;
    const int gBE    = (EP + EN + TPB - 1) / TPB;
    const int gN     = (NN + TPB - 1) / TPB;
    const int gND    = (NN * D + TPB - 1) / TPB;
    const int gNode8 = (NN + 7) / 8;
    const int nScanBlocks = (2 * NN + 1023) / 1024;
    constexpr int NBU = (NU + 127) / 128;

    // fork
    cudaEventRecord(evR, 0);
    if (sB) cudaStreamWaitEvent(sB, evR, 0);
    if (sC) cudaStreamWaitEvent(sC, evR, 0);

    // ---- chain B (sB): CSR -> conv x3 -> class ----
    cudaMemsetAsync(a_cnt2, 0, 2 * NN * sizeof(int), sB);
    cudaMemsetAsync(a_fill2, 0, 2 * NN * sizeof(int), sB);
    hist_kernel<<<gBE, TPB, 0, sB>>>(pe + EP, ne + EN);
    scan1_kernel<<<nScanBlocks, 1024, 0, sB>>>();
    scan2_kernel<<<1, 256, 0, sB>>>(nScanBlocks);
    scan3_kernel<<<(2 * NN + TPB - 1) / TPB, TPB, 0, sB>>>();
    fill_csr<<<gBE, TPB, 0, sB>>>(pe, ne);
    conv1_fused<<<gNode8, TPB, 0, sB>>>(sg_u, sg_i,
                                        c1_pl, c1_prw, c1_prb, c1_nl, c1_nrw, c1_nrb);   // sg -> y
    conv2_fused<<<gNode8, TPB, 0, sB>>>(cs_pl, cs_prw, cs_prb, cs_nl, cs_nrw, cs_nrb,
                                        (const float*)a_y, (float*)a_x);                 // y -> x
    conv2_fused<<<gNode8, TPB, 0, sB>>>(cs_pl + D * H2, cs_prw + H2 * H2, cs_prb + H2,
                                        cs_nl + D * H2, cs_nrw + H2 * H2, cs_nrb + H2,
                                        (const float*)a_x, (float*)a_y);                 // x -> y
    class_kernel<<<gEw, TPB, 0, sB>>>(ei, ei + E, (const float*)a_y, lin_w, lin_b);
    cudaEventRecord(evB, sB);

    // ---- chain C (sC): zeroing, LightGCN init, lg output copies ----
    cudaMemsetAsync(a_sums, 0, 2 * sizeof(float), sC);
    cudaMemsetAsync(a_deg, 0, NN * sizeof(float), sC);
    initacc_kernel<<<gND, TPB, 0, sC>>>(lg_u, lg_i);
    out_copy<<<gND, TPB, 0, sC>>>(lg_u, lg_i, out);
    cudaEventRecord(evC, sC);

    // ---- chain A (origin stream): GEMMs -> norms -> sim ----
    gemm2<<<2 * NBU, 256>>>(user_feat, W_user, b_user, food_feat, W_food, b_food);
    node_norms2<<<((NU + NF) * 32 + TPB - 1) / TPB, TPB>>>(metric_w);
    sim_kernel<<<gEw, TPB>>>(ei, ei + E, metric_w);

    // join
    cudaStreamWaitEvent(0, evB, 0);
    cudaStreamWaitEvent(0, evC, 0);

    // ---- tail: mask fusion + LightGCN + fused output ----
    sum_kernel<<<256, TPB>>>();
    wedge_kernel<<<gE, TPB>>>(ei, fusion_w);
    dis_kernel<<<gN, TPB>>>();
    norm_kernel<<<gE, TPB>>>(ei, ei + E);

    prop_kernel<<<gE16, TPB>>>(ei, ei + E, (const float*)a_xk, (float*)a_xk2);   // x1 -> xk2
    accadd_zero<<<gND, TPB>>>((const float*)a_xk2, (float*)a_xk);                // acc+=x1, zero xk
    prop_kernel<<<gE16, TPB>>>(ei, ei + E, (const float*)a_xk2, (float*)a_xk);   // x2 -> xk
    accadd_zero<<<gND, TPB>>>((const float*)a_xk, (float*)a_xk2);                // acc+=x2, zero xk2
    prop_kernel<<<gE16, TPB>>>(ei, ei + E, (const float*)a_xk, (float*)a_xk2);   // x3 -> xk2
    out_final<<<gND, TPB>>>((const float*)a_xk2, out);                           // out=(acc+x3)/4
}

// round 7
// speedup vs baseline: 1.9315x; 1.0824x over previous
#include <cuda_runtime.h>
#include <math.h>

// ---------------- problem constants ----------------
constexpr int NU = 50000, NF = 50000, NN = 100000;
constexpr int D  = 64,    H2 = 32,    FU = 256;
constexpr int E  = 500000, EP = 500000, EN = 500000;
constexpr int NH = 4;
constexpr float THRESH = 0.3f;

// persistent grids
constexpr int PG_EDGE = 1184;   // sim/class: 8 warps/block
constexpr int PG_CONV = 740;    // conv kernels
constexpr int PG_NRM  = 1184;

// ---------------- device scratch ----------------
__device__ float g_u[NU * D];
__device__ float g_f[NF * D];
__device__ float g_x[NN * D];
__device__ float g_y[NN * D];
__device__ float g_maskF[E];
__device__ float g_maskS[E];
__device__ float g_we[E];
__device__ float g_norm[E];
__device__ float g_deg[NN];
__device__ float g_xk[NN * D];
__device__ float g_xk2[NN * D];
__device__ float g_acc[NN * D];
__device__ float g_sums[2];
__device__ int   g_nnz;
__device__ float4 g_nau[NU];
__device__ float4 g_naf[NF];
__device__ int g_cnt2[2 * NN];
__device__ int g_ptr2[2 * NN];
__device__ int g_fill2[2 * NN];
__device__ int g_bsum[256];
__device__ int g_csrP[EP];
__device__ int g_csrN[EN];

// ---------------- GEMM: both matrices, 128x64 tile, 8x4 per thread ----------------
__global__ void gemm2(const float* __restrict__ fu, const float* __restrict__ Wu,
                      const float* __restrict__ bu,
                      const float* __restrict__ ff, const float* __restrict__ Wf,
                      const float* __restrict__ bf) {
    constexpr int NBU = (NU + 127) / 128;
    bool isU = blockIdx.x < NBU;
    const float* feat = isU ? fu : ff;
    const float* W    = isU ? Wu : Wf;
    const float* bias = isU ? bu : bf;
    float* out        = isU ? g_u : g_f;
    int rows          = isU ? NU : NF;
    int bx            = isU ? blockIdx.x : blockIdx.x - NBU;

    __shared__ float sA[32][132];
    __shared__ float sB[32][64];
    int tid = threadIdx.x;
    int tx = tid & 15, ty = tid >> 4;
    int row0 = bx * 128;
    float acc[8][4];
#pragma unroll
    for (int i = 0; i < 8; i++)
#pragma unroll
        for (int j = 0; j < 4; j++) acc[i][j] = 0.f;

    for (int k0 = 0; k0 < FU; k0 += 32) {
        int r = tid >> 1;
        int kk = (tid & 1) * 16;
        int grow = row0 + r;
        float4 v[4];
        if (grow < rows) {
            const float4* s = (const float4*)&feat[grow * FU + k0 + kk];
            v[0] = s[0]; v[1] = s[1]; v[2] = s[2]; v[3] = s[3];
        } else {
            v[0] = make_float4(0.f, 0.f, 0.f, 0.f); v[1] = v[0]; v[2] = v[0]; v[3] = v[0];
        }
#pragma unroll
        for (int q = 0; q < 4; q++) {
            sA[kk + q * 4 + 0][r] = v[q].x; sA[kk + q * 4 + 1][r] = v[q].y;
            sA[kk + q * 4 + 2][r] = v[q].z; sA[kk + q * 4 + 3][r] = v[q].w;
        }
        {
            int idx = tid * 8, kw = idx >> 6, cw = idx & 63;
            const float4* ws = (const float4*)&W[(k0 + kw) * D + cw];
            *(float4*)&sB[kw][cw]     = ws[0];
            *(float4*)&sB[kw][cw + 4] = ws[1];
        }
        __syncthreads();
#pragma unroll
        for (int k = 0; k < 32; k++) {
            float4 b  = *(float4*)&sB[k][tx * 4];
            float4 a0 = *(float4*)&sA[k][ty * 8];
            float4 a1 = *(float4*)&sA[k][ty * 8 + 4];
            acc[0][0] += a0.x * b.x; acc[0][1] += a0.x * b.y; acc[0][2] += a0.x * b.z; acc[0][3] += a0.x * b.w;
            acc[1][0] += a0.y * b.x; acc[1][1] += a0.y * b.y; acc[1][2] += a0.y * b.z; acc[1][3] += a0.y * b.w;
            acc[2][0] += a0.z * b.x; acc[2][1] += a0.z * b.y; acc[2][2] += a0.z * b.z; acc[2][3] += a0.z * b.w;
            acc[3][0] += a0.w * b.x; acc[3][1] += a0.w * b.y; acc[3][2] += a0.w * b.z; acc[3][3] += a0.w * b.w;
            acc[4][0] += a1.x * b.x; acc[4][1] += a1.x * b.y; acc[4][2] += a1.x * b.z; acc[4][3] += a1.x * b.w;
            acc[5][0] += a1.y * b.x; acc[5][1] += a1.y * b.y; acc[5][2] += a1.y * b.z; acc[5][3] += a1.y * b.w;
            acc[6][0] += a1.z * b.x; acc[6][1] += a1.z * b.y; acc[6][2] += a1.z * b.z; acc[6][3] += a1.z * b.w;
            acc[7][0] += a1.w * b.x; acc[7][1] += a1.w * b.y; acc[7][2] += a1.w * b.z; acc[7][3] += a1.w * b.w;
        }
        __syncthreads();
    }
    float4 bb = *(const float4*)&bias[tx * 4];
#pragma unroll
    for (int i = 0; i < 8; i++) {
        int grow = row0 + ty * 8 + i;
        if (grow < rows) {
            float4 o;
            o.x = fmaxf(acc[i][0] + bb.x, 0.f);
            o.y = fmaxf(acc[i][1] + bb.y, 0.f);
            o.z = fmaxf(acc[i][2] + bb.z, 0.f);
            o.w = fmaxf(acc[i][3] + bb.w, 0.f);
            *(float4*)&out[grow * D + tx * 4] = o;
        }
    }
}

// ---------------- per-node per-head norms (persistent) ----------------
__global__ void node_norms2(const float* __restrict__ mw) {
    __shared__ float smw[NH * D];
    if (threadIdx.x < NH * D) smw[threadIdx.x] = mw[threadIdx.x];
    __syncthreads();
    int w = threadIdx.x >> 5, lane = threadIdx.x & 31;
    for (int node = blockIdx.x * 8 + w; node < NU + NF; node += gridDim.x * 8) {
        const float* x; float4* o;
        if (node < NU) { x = &g_u[node * D]; o = &g_nau[node]; }
        else           { x = &g_f[(node - NU) * D]; o = &g_naf[node - NU]; }
        float x0 = x[lane], x1 = x[32 + lane];
        float s[NH];
#pragma unroll
        for (int h = 0; h < NH; h++) {
            float a0 = x0 * smw[h * D + lane];
            float a1 = x1 * smw[h * D + 32 + lane];
            s[h] = a0 * a0 + a1 * a1;
        }
#pragma unroll
        for (int off = 16; off; off >>= 1)
#pragma unroll
            for (int h = 0; h < NH; h++) s[h] += __shfl_xor_sync(0xffffffffu, s[h], off);
        if (lane == 0)
            *o = make_float4(fmaxf(sqrtf(s[0]), 1e-8f), fmaxf(sqrtf(s[1]), 1e-8f),
                             fmaxf(sqrtf(s[2]), 1e-8f), fmaxf(sqrtf(s[3]), 1e-8f));
    }
}

// ---------------- per-edge cosine similarity (persistent) ----------------
__global__ void sim_kernel(const int* __restrict__ e0, const int* __restrict__ e1,
                           const float* __restrict__ mw) {
    __shared__ float smw2[NH * D];
    if (threadIdx.x < NH * D) { float w = mw[threadIdx.x]; smw2[threadIdx.x] = w * w; }
    __syncthreads();
    int w = threadIdx.x >> 5, lane = threadIdx.x & 31;
    for (int e = blockIdx.x * 8 + w; e < E; e += gridDim.x * 8) {
        int a = e0[e], b = e1[e];
        float u0 = g_u[a * D + lane],  u1 = g_u[a * D + 32 + lane];
        float f0 = g_f[b * D + lane],  f1 = g_f[b * D + 32 + lane];
        float p0 = u0 * f0, p1 = u1 * f1;
        float d[NH];
#pragma unroll
        for (int h = 0; h < NH; h++)
            d[h] = p0 * smw2[h * D + lane] + p1 * smw2[h * D + 32 + lane];
#pragma unroll
        for (int off = 16; off; off >>= 1)
#pragma unroll
            for (int h = 0; h < NH; h++) d[h] += __shfl_xor_sync(0xffffffffu, d[h], off);
        if (lane == 0) {
            float4 na = g_nau[a], nb = g_naf[b];
            float sim = d[0] / (na.x * nb.x) + d[1] / (na.y * nb.y)
                      + d[2] / (na.z * nb.z) + d[3] / (na.w * nb.w);
            sim *= (1.f / NH);
            g_maskF[e] = (sim < THRESH) ? 0.f : sim;
        }
    }
}

// ---------------- CSR build ----------------
__global__ void hist_kernel(const int* __restrict__ pd, const int* __restrict__ nd) {
    int i = blockIdx.x * blockDim.x + threadIdx.x;
    if (i < EP) atomicAdd(&g_cnt2[pd[i]], 1);
    else {
        i -= EP;
        if (i < EN) atomicAdd(&g_cnt2[NN + nd[i]], 1);
    }
}

__global__ void scan1_kernel() {
    __shared__ int sh[1024];
    int i = blockIdx.x * 1024 + threadIdx.x;
    int v = (i < 2 * NN) ? g_cnt2[i] : 0;
    sh[threadIdx.x] = v;
    __syncthreads();
    for (int off = 1; off < 1024; off <<= 1) {
        int t = (threadIdx.x >= off) ? sh[threadIdx.x - off] : 0;
        __syncthreads();
        sh[threadIdx.x] += t;
        __syncthreads();
    }
    if (i < 2 * NN) g_ptr2[i] = sh[threadIdx.x] - v;
    if (threadIdx.x == 1023) g_bsum[blockIdx.x] = sh[1023];
}

__global__ void scan2_kernel(int nb) {
    __shared__ int sh[256];
    int v = (threadIdx.x < nb) ? g_bsum[threadIdx.x] : 0;
    sh[threadIdx.x] = v;
    __syncthreads();
    for (int off = 1; off < 256; off <<= 1) {
        int t = (threadIdx.x >= off) ? sh[threadIdx.x - off] : 0;
        __syncthreads();
        sh[threadIdx.x] += t;
        __syncthreads();
    }
    if (threadIdx.x < nb) g_bsum[threadIdx.x] = sh[threadIdx.x] - v;
}

__global__ void scan3_kernel() {
    int i = blockIdx.x * blockDim.x + threadIdx.x;
    if (i < 2 * NN) g_ptr2[i] += g_bsum[i >> 10];
}

__global__ void fill_csr(const int* __restrict__ pe, const int* __restrict__ ne) {
    int i = blockIdx.x * blockDim.x + threadIdx.x;
    if (i < EP) {
        int d = pe[EP + i];
        int slot = atomicAdd(&g_fill2[d], 1);
        g_csrP[g_ptr2[d] + slot] = pe[i];
    } else {
        i -= EP;
        if (i < EN) {
            int d = ne[EN + i];
            int slot = atomicAdd(&g_fill2[NN + d], 1);
            g_csrN[(g_ptr2[NN + d] - EP) + slot] = ne[i];
        }
    }
}

__device__ __forceinline__ float ld_sg(const float* __restrict__ sgu,
                                       const float* __restrict__ sgi, int s, int c) {
    return (s < NU) ? sgu[s * D + c] : sgi[(s - NU) * D + c];
}

// ---------------- fused conv layer 1 (persistent) ----------------
__global__ void conv1_fused(const float* __restrict__ sgu, const float* __restrict__ sgi,
                            const float* __restrict__ pl, const float* __restrict__ prw,
                            const float* __restrict__ prb,
                            const float* __restrict__ nl, const float* __restrict__ nrw,
                            const float* __restrict__ nrb) {
    __shared__ float s_pl[D * H2], s_prw[D * H2], s_nl[D * H2], s_nrw[D * H2];
    __shared__ float stage[8 * 192];
    for (int i = threadIdx.x; i < D * H2; i += 256) {
        s_pl[i] = pl[i]; s_prw[i] = prw[i]; s_nl[i] = nl[i]; s_nrw[i] = nrw[i];
    }
    __syncthreads();
    int w = threadIdx.x >> 5, c = threadIdx.x & 31;
    float* st = &stage[w * 192];
    for (int node = blockIdx.x * 8 + w; node < NN; node += gridDim.x * 8) {
        int p0 = g_ptr2[node], p1 = g_ptr2[node + 1];
        int n0 = g_ptr2[NN + node] - EP;
        int n1 = ((node == NN - 1) ? EN : (g_ptr2[NN + node + 1] - EP));
        float mp0 = 0.f, mp1 = 0.f, mn0 = 0.f, mn1 = 0.f;
        for (int j = p0; j < p1; j++) {
            int s = g_csrP[j];
            mp0 += ld_sg(sgu, sgi, s, c); mp1 += ld_sg(sgu, sgi, s, 32 + c);
        }
        for (int j = n0; j < n1; j++) {
            int s = g_csrN[j];
            mn0 += ld_sg(sgu, sgi, s, c); mn1 += ld_sg(sgu, sgi, s, 32 + c);
        }
        float invP = 1.f / fmaxf((float)(p1 - p0), 1.f);
        float invN = 1.f / fmaxf((float)(n1 - n0), 1.f);
        st[c]       = mp0 * invP; st[32 + c]  = mp1 * invP;
        st[64 + c]  = mn0 * invN; st[96 + c]  = mn1 * invN;
        st[128 + c] = ld_sg(sgu, sgi, node, c);
        st[160 + c] = ld_sg(sgu, sgi, node, 32 + c);
        __syncwarp();
        float accP = prb[c], accN = nrb[c];
#pragma unroll 8
        for (int k = 0; k < D; k++) {
            float mpk = st[k], mnk = st[64 + k], xk = st[128 + k];
            accP += mpk * s_pl[k * H2 + c] + xk * s_prw[k * H2 + c];
            accN += mnk * s_nl[k * H2 + c] + xk * s_nrw[k * H2 + c];
        }
        g_y[node * D + c]      = fmaxf(accP, 0.f);
        g_y[node * D + 32 + c] = fmaxf(accN, 0.f);
        __syncwarp();
    }
}

// ---------------- fused conv layers 2/3 (persistent) ----------------
__global__ void conv2_fused(const float* __restrict__ pl, const float* __restrict__ prw,
                            const float* __restrict__ prb,
                            const float* __restrict__ nl, const float* __restrict__ nrw,
                            const float* __restrict__ nrb,
                            const float* __restrict__ zin, float* __restrict__ zout) {
    __shared__ float s_pl[D * H2], s_nl[D * H2], s_prw[H2 * H2], s_nrw[H2 * H2];
    __shared__ float stage[8 * 192];
    for (int i = threadIdx.x; i < D * H2; i += 256) { s_pl[i] = pl[i]; s_nl[i] = nl[i]; }
    for (int i = threadIdx.x; i < H2 * H2; i += 256) { s_prw[i] = prw[i]; s_nrw[i] = nrw[i]; }
    __syncthreads();
    int w = threadIdx.x >> 5, c = threadIdx.x & 31;
    float* st = &stage[w * 192];
    for (int node = blockIdx.x * 8 + w; node < NN; node += gridDim.x * 8) {
        int p0 = g_ptr2[node], p1 = g_ptr2[node + 1];
        int n0 = g_ptr2[NN + node] - EP;
        int n1 = ((node == NN - 1) ? EN : (g_ptr2[NN + node + 1] - EP));
        float pp = 0.f, pn = 0.f, np_ = 0.f, nn = 0.f;
        for (int j = p0; j < p1; j++) {
            int s = g_csrP[j];
            pp += zin[s * D + c]; pn += zin[s * D + 32 + c];
        }
        for (int j = n0; j < n1; j++) {
            int s = g_csrN[j];
            np_ += zin[s * D + c]; nn += zin[s * D + 32 + c];
        }
        float invP = 1.f / fmaxf((float)(p1 - p0), 1.f);
        float invN = 1.f / fmaxf((float)(n1 - n0), 1.f);
        st[c]       = pp * invP;  st[32 + c] = nn * invN;
        st[64 + c]  = pn * invP;  st[96 + c] = np_ * invN;
        st[128 + c] = zin[node * D + c];
        st[160 + c] = zin[node * D + 32 + c];
        __syncwarp();
        float accP = prb[c], accN = nrb[c];
#pragma unroll 8
        for (int k = 0; k < D; k++) {
            accP += st[k]      * s_pl[k * H2 + c];
            accN += st[64 + k] * s_nl[k * H2 + c];
        }
#pragma unroll 8
        for (int k = 0; k < H2; k++) {
            accP += st[128 + k] * s_prw[k * H2 + c];
            accN += st[160 + k] * s_nrw[k * H2 + c];
        }
        zout[node * D + c]      = fmaxf(accP, 0.f);
        zout[node * D + 32 + c] = fmaxf(accN, 0.f);
        __syncwarp();
    }
}

// ---------------- per-edge classifier (persistent) ----------------
__global__ void class_kernel(const int* __restrict__ e0, const int* __restrict__ e1,
                             const float* __restrict__ z,
                             const float* __restrict__ lw, const float* __restrict__ lb) {
    __shared__ float slw[2 * D * 3];
    __shared__ float slb[3];
    for (int i = threadIdx.x; i < 2 * D * 3; i += 256) slw[i] = lw[i];
    if (threadIdx.x < 3) slb[threadIdx.x] = lb[threadIdx.x];
    __syncthreads();
    int w = threadIdx.x >> 5, lane = threadIdx.x & 31;
    for (int e = blockIdx.x * 8 + w; e < E; e += gridDim.x * 8) {
        int a = e0[e], b = e1[e];
        float za0 = z[a * D + lane], za1 = z[a * D + 32 + lane];
        float zb0 = z[b * D + lane], zb1 = z[b * D + 32 + lane];
        float v0 = za0 * slw[lane * 3 + 0] + za1 * slw[(32 + lane) * 3 + 0]
                 + zb0 * slw[(64 + lane) * 3 + 0] + zb1 * slw[(96 + lane) * 3 + 0];
        float v1 = za0 * slw[lane * 3 + 1] + za1 * slw[(32 + lane) * 3 + 1]
                 + zb0 * slw[(64 + lane) * 3 + 1] + zb1 * slw[(96 + lane) * 3 + 1];
        float v2 = za0 * slw[lane * 3 + 2] + za1 * slw[(32 + lane) * 3 + 2]
                 + zb0 * slw[(64 + lane) * 3 + 2] + zb1 * slw[(96 + lane) * 3 + 2];
#pragma unroll
        for (int off = 16; off; off >>= 1) {
            v0 += __shfl_xor_sync(0xffffffffu, v0, off);
            v1 += __shfl_xor_sync(0xffffffffu, v1, off);
            v2 += __shfl_xor_sync(0xffffffffu, v2, off);
        }
        if (lane == 0) {
            v0 += slb[0]; v1 += slb[1]; v2 += slb[2];
            int cls = 0; float best = v0;
            if (v1 > best) { best = v1; cls = 1; }
            if (v2 > best) { cls = 2; }
            g_maskS[e] = (float)(cls - 1);
        }
    }
}

// ---------------- mask fusion path ----------------
__global__ void sum_kernel() {
    float sf = 0.f, ss = 0.f;
    for (int i = blockIdx.x * blockDim.x + threadIdx.x; i < E; i += gridDim.x * blockDim.x) {
        sf += fabsf(g_maskF[i]);
        ss += fabsf(g_maskS[i]);
    }
#pragma unroll
    for (int off = 16; off; off >>= 1) {
        sf += __shfl_xor_sync(0xffffffffu, sf, off);
        ss += __shfl_xor_sync(0xffffffffu, ss, off);
    }
    __shared__ float shf[8], shs[8];
    int w = threadIdx.x >> 5, l = threadIdx.x & 31;
    if (l == 0) { shf[w] = sf; shs[w] = ss; }
    __syncthreads();
    if (threadIdx.x == 0) {
        float a = 0.f, b = 0.f;
        for (int i = 0; i < 8; i++) { a += shf[i]; b += shs[i]; }
        atomicAdd(&g_sums[0], a);
        atomicAdd(&g_sums[1], b);
    }
}

__global__ void wedge_kernel(const int* __restrict__ e0, const float* __restrict__ fw) {
    int i = blockIdx.x * blockDim.x + threadIdx.x;
    if (i >= E) return;
    float w0 = fw[0], w1 = fw[1], w2 = fw[2];
    float m = fmaxf(w0, fmaxf(w1, w2));
    float ex0 = expf(w0 - m), ex1 = expf(w1 - m), ex2 = expf(w2 - m);
    float s = ex0 + ex1 + ex2;
    float sw0 = ex0 / s, sw1 = ex1 / s, sw2 = ex2 / s;
    float nO = 1.f / (float)E;
    float nF = g_maskF[i] / fmaxf(g_sums[0], 1e-12f);
    float nS = g_maskS[i] / fmaxf(g_sums[1], 1e-12f);
    float fused = sw0 * nO + sw1 * nF + sw2 * nS;
    float w = (fused > 0.5f) ? 1.f : 0.f;
    g_we[i] = w;
    if (w != 0.f) atomicAdd(&g_deg[e0[i]], w);
    unsigned msk = __ballot_sync(__activemask(), w != 0.f);
    if ((threadIdx.x & 31) == 0 && msk) atomicAdd(&g_nnz, __popc(msk));
}

__global__ void dis_kernel() {
    int i = blockIdx.x * blockDim.x + threadIdx.x;
    if (i < NN) {
        float d = g_deg[i];
        g_deg[i] = (d > 0.f) ? rsqrtf(fmaxf(d, 1e-12f)) : 0.f;
    }
}

__global__ void norm_kernel(const int* __restrict__ e0, const int* __restrict__ e1) {
    int i = blockIdx.x * blockDim.x + threadIdx.x;
    if (i >= E) return;
    g_norm[i] = g_deg[e0[i]] * g_we[i] * g_deg[e1[i]];
}

// ---------------- LightGCN ----------------
// init acc/xk/xk2 AND write lg embedding copies to out (fused)
__global__ void initacc_out(const float* __restrict__ lgu, const float* __restrict__ lgi,
                            float* __restrict__ out) {
    int i = blockIdx.x * blockDim.x + threadIdx.x;
    if (i >= NN * D) return;
    constexpr int A = NU * D;
    float v;
    if (i < A) { v = lgu[i];     out[A + i]     = v; }   // lg_u at [A:2A)
    else       { v = lgi[i - A]; out[2 * A + i] = v; }   // lg_i at [3A:4A)
    g_acc[i] = v;
    g_xk[i]  = v;
    g_xk2[i] = 0.f;
}

__device__ __forceinline__ void red_add_v4(float* p, float x, float y, float z, float w) {
    asm volatile("red.global.add.v4.f32 [%0], {%1,%2,%3,%4};"
                 :: "l"(p), "f"(x), "f"(y), "f"(z), "f"(w) : "memory");
}

__global__ void prop_kernel(const int* __restrict__ e0, const int* __restrict__ e1,
                            const float* __restrict__ xin, float* __restrict__ xout) {
    if (g_nnz == 0) return;
    int t = blockIdx.x * blockDim.x + threadIdx.x;
    int e = t >> 4;
    if (e >= E) return;
    float nm = g_norm[e];
    if (nm == 0.f) return;
    int c = (t & 15) * 4;
    int s = e1[e], d = e0[e];
    float4 v = *(const float4*)&xin[s * D + c];
    red_add_v4(&xout[d * D + c], nm * v.x, nm * v.y, nm * v.z, nm * v.w);
}

__global__ void accadd_zero(const float* __restrict__ xnew, float* __restrict__ xold) {
    if (g_nnz == 0) return;   // xnew is all zeros and xold untouched-by-prop => acc unchanged
    int i = blockIdx.x * blockDim.x + threadIdx.x;
    if (i < NN * D) { g_acc[i] += xnew[i]; xold[i] = 0.f; }
}

__global__ void out_final(const float* __restrict__ x3, float* __restrict__ out) {
    int i = blockIdx.x * blockDim.x + threadIdx.x;
    if (i >= NN * D) return;
    constexpr int A = NU * D;
    float v = (g_acc[i] + x3[i]) * 0.25f;
    if (i < A) out[i]     = v;
    else       out[A + i] = v;
}

// ---------------- launch ----------------
extern "C" void kernel_launch(void* const* d_in, const int* in_sizes, int n_in,
                              void* d_out, int out_size) {
    const float* user_feat = (const float*)d_in[0];
    const float* food_feat = (const float*)d_in[1];
    const int*   ei        = (const int*)d_in[2];
    const int*   pe        = (const int*)d_in[3];
    const int*   ne        = (const int*)d_in[4];
    const float* W_user    = (const float*)d_in[5];
    const float* b_user    = (const float*)d_in[6];
    const float* W_food    = (const float*)d_in[7];
    const float* b_food    = (const float*)d_in[8];
    const float* metric_w  = (const float*)d_in[9];
    const float* fusion_w  = (const float*)d_in[10];
    const float* sg_u      = (const float*)d_in[11];
    const float* sg_i      = (const float*)d_in[12];
    const float* c1_pl     = (const float*)d_in[13];
    const float* c1_prw    = (const float*)d_in[14];
    const float* c1_prb    = (const float*)d_in[15];
    const float* c1_nl     = (const float*)d_in[16];
    const float* c1_nrw    = (const float*)d_in[17];
    const float* c1_nrb    = (const float*)d_in[18];
    const float* cs_pl     = (const float*)d_in[19];
    const float* cs_prw    = (const float*)d_in[20];
    const float* cs_prb    = (const float*)d_in[21];
    const float* cs_nl     = (const float*)d_in[22];
    const float* cs_nrw    = (const float*)d_in[23];
    const float* cs_nrb    = (const float*)d_in[24];
    const float* lin_w     = (const float*)d_in[25];
    const float* lin_b     = (const float*)d_in[26];
    const float* lg_u      = (const float*)d_in[27];
    const float* lg_i      = (const float*)d_in[28];
    float* out = (float*)d_out;

    void *a_x, *a_y, *a_cnt2, *a_fill2, *a_deg, *a_sums, *a_nnz, *a_xk, *a_xk2;
    cudaGetSymbolAddress(&a_x, g_x);
    cudaGetSymbolAddress(&a_y, g_y);
    cudaGetSymbolAddress(&a_cnt2, g_cnt2);
    cudaGetSymbolAddress(&a_fill2, g_fill2);
    cudaGetSymbolAddress(&a_deg, g_deg);
    cudaGetSymbolAddress(&a_sums, g_sums);
    cudaGetSymbolAddress(&a_nnz, g_nnz);
    cudaGetSymbolAddress(&a_xk, g_xk);
    cudaGetSymbolAddress(&a_xk2, g_xk2);

    static cudaStream_t sB = 0, sC = 0;
    static cudaEvent_t evR = 0, evB = 0, evC = 0;
    static bool s_init = false;
    if (!s_init) {
        cudaStreamCreateWithFlags(&sB, cudaStreamNonBlocking);
        cudaStreamCreateWithFlags(&sC, cudaStreamNonBlocking);
        cudaEventCreateWithFlags(&evR, cudaEventDisableTiming);
        cudaEventCreateWithFlags(&evB, cudaEventDisableTiming);
        cudaEventCreateWithFlags(&evC, cudaEventDisableTiming);
        s_init = true;
    }

    const int TPB = 256;
    const int gE     = (E + TPB - 1) / TPB;
    const int gE16   = (E * 16 + TPB - 1) / TPB;
    const int gBE    = (EP + EN + TPB - 1) / TPB;
    const int gN     = (NN + TPB - 1) / TPB;
    const int gND    = (NN * D + TPB - 1) / TPB;
    const int nScanBlocks = (2 * NN + 1023) / 1024;
    constexpr int NBU = (NU + 127) / 128;

    // fork
    cudaEventRecord(evR, 0);
    if (sB) cudaStreamWaitEvent(sB, evR, 0);
    if (sC) cudaStreamWaitEvent(sC, evR, 0);

    // ---- chain B (sB): CSR -> conv x3 -> class ----
    cudaMemsetAsync(a_cnt2, 0, 2 * NN * sizeof(int), sB);
    cudaMemsetAsync(a_fill2, 0, 2 * NN * sizeof(int), sB);
    hist_kernel<<<gBE, TPB, 0, sB>>>(pe + EP, ne + EN);
    scan1_kernel<<<nScanBlocks, 1024, 0, sB>>>();
    scan2_kernel<<<1, 256, 0, sB>>>(nScanBlocks);
    scan3_kernel<<<(2 * NN + TPB - 1) / TPB, TPB, 0, sB>>>();
    fill_csr<<<gBE, TPB, 0, sB>>>(pe, ne);
    conv1_fused<<<PG_CONV, TPB, 0, sB>>>(sg_u, sg_i,
                                         c1_pl, c1_prw, c1_prb, c1_nl, c1_nrw, c1_nrb);
    conv2_fused<<<PG_CONV, TPB, 0, sB>>>(cs_pl, cs_prw, cs_prb, cs_nl, cs_nrw, cs_nrb,
                                         (const float*)a_y, (float*)a_x);
    conv2_fused<<<PG_CONV, TPB, 0, sB>>>(cs_pl + D * H2, cs_prw + H2 * H2, cs_prb + H2,
                                         cs_nl + D * H2, cs_nrw + H2 * H2, cs_nrb + H2,
                                         (const float*)a_x, (float*)a_y);
    class_kernel<<<PG_EDGE, TPB, 0, sB>>>(ei, ei + E, (const float*)a_y, lin_w, lin_b);
    cudaEventRecord(evB, sB);

    // ---- chain C (sC): zeroing, LightGCN init + lg output copies ----
    cudaMemsetAsync(a_sums, 0, 2 * sizeof(float), sC);
    cudaMemsetAsync(a_nnz, 0, sizeof(int), sC);
    cudaMemsetAsync(a_deg, 0, NN * sizeof(float), sC);
    initacc_out<<<gND, TPB, 0, sC>>>(lg_u, lg_i, out);
    cudaEventRecord(evC, sC);

    // ---- chain A (origin): GEMMs -> norms -> sim ----
    gemm2<<<2 * NBU, 256>>>(user_feat, W_user, b_user, food_feat, W_food, b_food);
    node_norms2<<<PG_NRM, TPB>>>(metric_w);
    sim_kernel<<<PG_EDGE, TPB>>>(ei, ei + E, metric_w);

    // join
    cudaStreamWaitEvent(0, evB, 0);
    cudaStreamWaitEvent(0, evC, 0);

    // ---- tail ----
    sum_kernel<<<256, TPB>>>();
    wedge_kernel<<<gE, TPB>>>(ei, fusion_w);
    dis_kernel<<<gN, TPB>>>();
    norm_kernel<<<gE, TPB>>>(ei, ei + E);

    prop_kernel<<<gE16, TPB>>>(ei, ei + E, (const float*)a_xk, (float*)a_xk2);
    accadd_zero<<<gND, TPB>>>((const float*)a_xk2, (float*)a_xk);
    prop_kernel<<<gE16, TPB>>>(ei, ei + E, (const float*)a_xk2, (float*)a_xk);
    accadd_zero<<<gND, TPB>>>((const float*)a_xk, (float*)a_xk2);
    prop_kernel<<<gE16, TPB>>>(ei, ei + E, (const float*)a_xk, (float*)a_xk2);
    out_final<<<gND, TPB>>>((const float*)a_xk2, out);
}

// round 9
// speedup vs baseline: 2.2415x; 1.1605x over previous
#include <cuda_runtime.h>
#include <math.h>

// ---------------- problem constants ----------------
constexpr int NU = 50000, NF = 50000, NN = 100000;
constexpr int D  = 64,    H2 = 32,    FU = 256;
constexpr int E  = 500000, EP = 500000, EN = 500000;
constexpr int NH = 4;
constexpr float THRESH = 0.3f;

// persistent grids
constexpr int PG_EDGE = 1184;
constexpr int PG_CONV = 740;
constexpr int PG_NRM  = 1184;
constexpr int PG_TAIL = 1184;

// ---------------- device scratch ----------------
__device__ float g_u[NU * D];
__device__ float g_f[NF * D];
__device__ float g_x[NN * D];
__device__ float g_y[NN * D];
__device__ float g_maskF[E];
__device__ float g_maskS[E];
__device__ float g_we[E];
__device__ float g_norm[E];
__device__ float g_deg[NN];
__device__ float g_xk[NN * D];
__device__ float g_xk2[NN * D];
__device__ float g_acc[NN * D];
__device__ float g_sums[2];
__device__ int   g_nnz;
__device__ float4 g_nau[NU];
__device__ float4 g_naf[NF];
__device__ int g_cnt2[2 * NN];
__device__ int g_ptr2[2 * NN];
__device__ int g_fill2[2 * NN];
__device__ int g_bsum[256];
__device__ int g_csrP[EP];
__device__ int g_csrN[EN];

// ---------------- GEMM: both matrices, 128x64 tile, 8x4 per thread ----------------
__global__ void gemm2(const float* __restrict__ fu, const float* __restrict__ Wu,
                      const float* __restrict__ bu,
                      const float* __restrict__ ff, const float* __restrict__ Wf,
                      const float* __restrict__ bf) {
    constexpr int NBU = (NU + 127) / 128;
    bool isU = blockIdx.x < NBU;
    const float* feat = isU ? fu : ff;
    const float* W    = isU ? Wu : Wf;
    const float* bias = isU ? bu : bf;
    float* out        = isU ? g_u : g_f;
    int rows          = isU ? NU : NF;
    int bx            = isU ? blockIdx.x : blockIdx.x - NBU;

    __shared__ float sA[32][132];
    __shared__ float sB[32][64];
    int tid = threadIdx.x;
    int tx = tid & 15, ty = tid >> 4;
    int row0 = bx * 128;
    float acc[8][4];
#pragma unroll
    for (int i = 0; i < 8; i++)
#pragma unroll
        for (int j = 0; j < 4; j++) acc[i][j] = 0.f;

    for (int k0 = 0; k0 < FU; k0 += 32) {
        int r = tid >> 1;
        int kk = (tid & 1) * 16;
        int grow = row0 + r;
        float4 v[4];
        if (grow < rows) {
            const float4* s = (const float4*)&feat[grow * FU + k0 + kk];
            v[0] = s[0]; v[1] = s[1]; v[2] = s[2]; v[3] = s[3];
        } else {
            v[0] = make_float4(0.f, 0.f, 0.f, 0.f); v[1] = v[0]; v[2] = v[0]; v[3] = v[0];
        }
#pragma unroll
        for (int q = 0; q < 4; q++) {
            sA[kk + q * 4 + 0][r] = v[q].x; sA[kk + q * 4 + 1][r] = v[q].y;
            sA[kk + q * 4 + 2][r] = v[q].z; sA[kk + q * 4 + 3][r] = v[q].w;
        }
        {
            int idx = tid * 8, kw = idx >> 6, cw = idx & 63;
            const float4* ws = (const float4*)&W[(k0 + kw) * D + cw];
            *(float4*)&sB[kw][cw]     = ws[0];
            *(float4*)&sB[kw][cw + 4] = ws[1];
        }
        __syncthreads();
#pragma unroll
        for (int k = 0; k < 32; k++) {
            float4 b  = *(float4*)&sB[k][tx * 4];
            float4 a0 = *(float4*)&sA[k][ty * 8];
            float4 a1 = *(float4*)&sA[k][ty * 8 + 4];
            acc[0][0] += a0.x * b.x; acc[0][1] += a0.x * b.y; acc[0][2] += a0.x * b.z; acc[0][3] += a0.x * b.w;
            acc[1][0] += a0.y * b.x; acc[1][1] += a0.y * b.y; acc[1][2] += a0.y * b.z; acc[1][3] += a0.y * b.w;
            acc[2][0] += a0.z * b.x; acc[2][1] += a0.z * b.y; acc[2][2] += a0.z * b.z; acc[2][3] += a0.z * b.w;
            acc[3][0] += a0.w * b.x; acc[3][1] += a0.w * b.y; acc[3][2] += a0.w * b.z; acc[3][3] += a0.w * b.w;
            acc[4][0] += a1.x * b.x; acc[4][1] += a1.x * b.y; acc[4][2] += a1.x * b.z; acc[4][3] += a1.x * b.w;
            acc[5][0] += a1.y * b.x; acc[5][1] += a1.y * b.y; acc[5][2] += a1.y * b.z; acc[5][3] += a1.y * b.w;
            acc[6][0] += a1.z * b.x; acc[6][1] += a1.z * b.y; acc[6][2] += a1.z * b.z; acc[6][3] += a1.z * b.w;
            acc[7][0] += a1.w * b.x; acc[7][1] += a1.w * b.y; acc[7][2] += a1.w * b.z; acc[7][3] += a1.w * b.w;
        }
        __syncthreads();
    }
    float4 bb = *(const float4*)&bias[tx * 4];
#pragma unroll
    for (int i = 0; i < 8; i++) {
        int grow = row0 + ty * 8 + i;
        if (grow < rows) {
            float4 o;
            o.x = fmaxf(acc[i][0] + bb.x, 0.f);
            o.y = fmaxf(acc[i][1] + bb.y, 0.f);
            o.z = fmaxf(acc[i][2] + bb.z, 0.f);
            o.w = fmaxf(acc[i][3] + bb.w, 0.f);
            *(float4*)&out[grow * D + tx * 4] = o;
        }
    }
}

// ---------------- per-node per-head norms (persistent) ----------------
__global__ void node_norms2(const float* __restrict__ mw) {
    __shared__ float smw[NH * D];
    if (threadIdx.x < NH * D) smw[threadIdx.x] = mw[threadIdx.x];
    __syncthreads();
    int w = threadIdx.x >> 5, lane = threadIdx.x & 31;
    for (int node = blockIdx.x * 8 + w; node < NU + NF; node += gridDim.x * 8) {
        const float* x; float4* o;
        if (node < NU) { x = &g_u[node * D]; o = &g_nau[node]; }
        else           { x = &g_f[(node - NU) * D]; o = &g_naf[node - NU]; }
        float x0 = x[lane], x1 = x[32 + lane];
        float s[NH];
#pragma unroll
        for (int h = 0; h < NH; h++) {
            float a0 = x0 * smw[h * D + lane];
            float a1 = x1 * smw[h * D + 32 + lane];
            s[h] = a0 * a0 + a1 * a1;
        }
#pragma unroll
        for (int off = 16; off; off >>= 1)
#pragma unroll
            for (int h = 0; h < NH; h++) s[h] += __shfl_xor_sync(0xffffffffu, s[h], off);
        if (lane == 0)
            *o = make_float4(fmaxf(sqrtf(s[0]), 1e-8f), fmaxf(sqrtf(s[1]), 1e-8f),
                             fmaxf(sqrtf(s[2]), 1e-8f), fmaxf(sqrtf(s[3]), 1e-8f));
    }
}

// ---------------- per-edge cosine similarity (persistent) + |maskF| sum ----------------
__global__ void sim_kernel(const int* __restrict__ e0, const int* __restrict__ e1,
                           const float* __restrict__ mw) {
    __shared__ float smw2[NH * D];
    __shared__ float psum[8];
    if (threadIdx.x < NH * D) { float w = mw[threadIdx.x]; smw2[threadIdx.x] = w * w; }
    __syncthreads();
    int w = threadIdx.x >> 5, lane = threadIdx.x & 31;
    float locsum = 0.f;
    for (int e = blockIdx.x * 8 + w; e < E; e += gridDim.x * 8) {
        int a = e0[e], b = e1[e];
        float u0 = g_u[a * D + lane],  u1 = g_u[a * D + 32 + lane];
        float f0 = g_f[b * D + lane],  f1 = g_f[b * D + 32 + lane];
        float p0 = u0 * f0, p1 = u1 * f1;
        float d[NH];
#pragma unroll
        for (int h = 0; h < NH; h++)
            d[h] = p0 * smw2[h * D + lane] + p1 * smw2[h * D + 32 + lane];
#pragma unroll
        for (int off = 16; off; off >>= 1)
#pragma unroll
            for (int h = 0; h < NH; h++) d[h] += __shfl_xor_sync(0xffffffffu, d[h], off);
        if (lane == 0) {
            float4 na = g_nau[a], nb = g_naf[b];
            float sim = d[0] / (na.x * nb.x) + d[1] / (na.y * nb.y)
                      + d[2] / (na.z * nb.z) + d[3] / (na.w * nb.w);
            sim *= (1.f / NH);
            float m = (sim < THRESH) ? 0.f : sim;
            g_maskF[e] = m;
            locsum += fabsf(m);
        }
    }
    if (lane == 0) psum[w] = locsum;
    __syncthreads();
    if (threadIdx.x == 0) {
        float t = 0.f;
        for (int i = 0; i < 8; i++) t += psum[i];
        if (t != 0.f) atomicAdd(&g_sums[0], t);
    }
}

// ---------------- CSR build ----------------
__global__ void hist_kernel(const int* __restrict__ pd, const int* __restrict__ nd) {
    int i = blockIdx.x * blockDim.x + threadIdx.x;
    if (i < EP) atomicAdd(&g_cnt2[pd[i]], 1);
    else {
        i -= EP;
        if (i < EN) atomicAdd(&g_cnt2[NN + nd[i]], 1);
    }
}

__global__ void scan1_kernel() {
    __shared__ int sh[1024];
    int i = blockIdx.x * 1024 + threadIdx.x;
    int v = (i < 2 * NN) ? g_cnt2[i] : 0;
    sh[threadIdx.x] = v;
    __syncthreads();
    for (int off = 1; off < 1024; off <<= 1) {
        int t = (threadIdx.x >= off) ? sh[threadIdx.x - off] : 0;
        __syncthreads();
        sh[threadIdx.x] += t;
        __syncthreads();
    }
    if (i < 2 * NN) g_ptr2[i] = sh[threadIdx.x] - v;
    if (threadIdx.x == 1023) g_bsum[blockIdx.x] = sh[1023];
}

__global__ void scan2_kernel(int nb) {
    __shared__ int sh[256];
    int v = (threadIdx.x < nb) ? g_bsum[threadIdx.x] : 0;
    sh[threadIdx.x] = v;
    __syncthreads();
    for (int off = 1; off < 256; off <<= 1) {
        int t = (threadIdx.x >= off) ? sh[threadIdx.x - off] : 0;
        __syncthreads();
        sh[threadIdx.x] += t;
        __syncthreads();
    }
    if (threadIdx.x < nb) g_bsum[threadIdx.x] = sh[threadIdx.x] - v;
}

__global__ void scan3_kernel() {
    int i = blockIdx.x * blockDim.x + threadIdx.x;
    if (i < 2 * NN) g_ptr2[i] += g_bsum[i >> 10];
}

__global__ void fill_csr(const int* __restrict__ pe, const int* __restrict__ ne) {
    int i = blockIdx.x * blockDim.x + threadIdx.x;
    if (i < EP) {
        int d = pe[EP + i];
        int slot = atomicAdd(&g_fill2[d], 1);
        g_csrP[g_ptr2[d] + slot] = pe[i];
    } else {
        i -= EP;
        if (i < EN) {
            int d = ne[EN + i];
            int slot = atomicAdd(&g_fill2[NN + d], 1);
            g_csrN[(g_ptr2[NN + d] - EP) + slot] = ne[i];
        }
    }
}

__device__ __forceinline__ float ld_sg(const float* __restrict__ sgu,
                                       const float* __restrict__ sgi, int s, int c) {
    return (s < NU) ? sgu[s * D + c] : sgi[(s - NU) * D + c];
}

// ---------------- fused conv layer 1 (persistent, x2 unrolled gathers) ----------------
__global__ void conv1_fused(const float* __restrict__ sgu, const float* __restrict__ sgi,
                            const float* __restrict__ pl, const float* __restrict__ prw,
                            const float* __restrict__ prb,
                            const float* __restrict__ nl, const float* __restrict__ nrw,
                            const float* __restrict__ nrb) {
    __shared__ float s_pl[D * H2], s_prw[D * H2], s_nl[D * H2], s_nrw[D * H2];
    __shared__ float stage[8 * 192];
    for (int i = threadIdx.x; i < D * H2; i += 256) {
        s_pl[i] = pl[i]; s_prw[i] = prw[i]; s_nl[i] = nl[i]; s_nrw[i] = nrw[i];
    }
    __syncthreads();
    int w = threadIdx.x >> 5, c = threadIdx.x & 31;
    float* st = &stage[w * 192];
    for (int node = blockIdx.x * 8 + w; node < NN; node += gridDim.x * 8) {
        int p0 = g_ptr2[node], p1 = g_ptr2[node + 1];
        int n0 = g_ptr2[NN + node] - EP;
        int n1 = ((node == NN - 1) ? EN : (g_ptr2[NN + node + 1] - EP));
        float mp0 = 0.f, mp1 = 0.f, mn0 = 0.f, mn1 = 0.f;
        int j = p0;
        for (; j + 1 < p1; j += 2) {
            int s0 = g_csrP[j], s1 = g_csrP[j + 1];
            float a0 = ld_sg(sgu, sgi, s0, c),      b0 = ld_sg(sgu, sgi, s0, 32 + c);
            float a1 = ld_sg(sgu, sgi, s1, c),      b1 = ld_sg(sgu, sgi, s1, 32 + c);
            mp0 += a0 + a1; mp1 += b0 + b1;
        }
        if (j < p1) {
            int s0 = g_csrP[j];
            mp0 += ld_sg(sgu, sgi, s0, c); mp1 += ld_sg(sgu, sgi, s0, 32 + c);
        }
        j = n0;
        for (; j + 1 < n1; j += 2) {
            int s0 = g_csrN[j], s1 = g_csrN[j + 1];
            float a0 = ld_sg(sgu, sgi, s0, c),      b0 = ld_sg(sgu, sgi, s0, 32 + c);
            float a1 = ld_sg(sgu, sgi, s1, c),      b1 = ld_sg(sgu, sgi, s1, 32 + c);
            mn0 += a0 + a1; mn1 += b0 + b1;
        }
        if (j < n1) {
            int s0 = g_csrN[j];
            mn0 += ld_sg(sgu, sgi, s0, c); mn1 += ld_sg(sgu, sgi, s0, 32 + c);
        }
        float invP = 1.f / fmaxf((float)(p1 - p0), 1.f);
        float invN = 1.f / fmaxf((float)(n1 - n0), 1.f);
        st[c]       = mp0 * invP; st[32 + c]  = mp1 * invP;
        st[64 + c]  = mn0 * invN; st[96 + c]  = mn1 * invN;
        st[128 + c] = ld_sg(sgu, sgi, node, c);
        st[160 + c] = ld_sg(sgu, sgi, node, 32 + c);
        __syncwarp();
        float accP = prb[c], accN = nrb[c];
#pragma unroll 8
        for (int k = 0; k < D; k++) {
            float mpk = st[k], mnk = st[64 + k], xk = st[128 + k];
            accP += mpk * s_pl[k * H2 + c] + xk * s_prw[k * H2 + c];
            accN += mnk * s_nl[k * H2 + c] + xk * s_nrw[k * H2 + c];
        }
        g_y[node * D + c]      = fmaxf(accP, 0.f);
        g_y[node * D + 32 + c] = fmaxf(accN, 0.f);
        __syncwarp();
    }
}

// ---------------- fused conv layers 2/3 (persistent, x2 unrolled gathers) ----------------
__global__ void conv2_fused(const float* __restrict__ pl, const float* __restrict__ prw,
                            const float* __restrict__ prb,
                            const float* __restrict__ nl, const float* __restrict__ nrw,
                            const float* __restrict__ nrb,
                            const float* __restrict__ zin, float* __restrict__ zout) {
    __shared__ float s_pl[D * H2], s_nl[D * H2], s_prw[H2 * H2], s_nrw[H2 * H2];
    __shared__ float stage[8 * 192];
    for (int i = threadIdx.x; i < D * H2; i += 256) { s_pl[i] = pl[i]; s_nl[i] = nl[i]; }
    for (int i = threadIdx.x; i < H2 * H2; i += 256) { s_prw[i] = prw[i]; s_nrw[i] = nrw[i]; }
    __syncthreads();
    int w = threadIdx.x >> 5, c = threadIdx.x & 31;
    float* st = &stage[w * 192];
    for (int node = blockIdx.x * 8 + w; node < NN; node += gridDim.x * 8) {
        int p0 = g_ptr2[node], p1 = g_ptr2[node + 1];
        int n0 = g_ptr2[NN + node] - EP;
        int n1 = ((node == NN - 1) ? EN : (g_ptr2[NN + node + 1] - EP));
        float pp = 0.f, pn = 0.f, np_ = 0.f, nn = 0.f;
        int j = p0;
        for (; j + 1 < p1; j += 2) {
            int s0 = g_csrP[j], s1 = g_csrP[j + 1];
            float a0 = zin[s0 * D + c], b0 = zin[s0 * D + 32 + c];
            float a1 = zin[s1 * D + c], b1 = zin[s1 * D + 32 + c];
            pp += a0 + a1; pn += b0 + b1;
        }
        if (j < p1) {
            int s0 = g_csrP[j];
            pp += zin[s0 * D + c]; pn += zin[s0 * D + 32 + c];
        }
        j = n0;
        for (; j + 1 < n1; j += 2) {
            int s0 = g_csrN[j], s1 = g_csrN[j + 1];
            float a0 = zin[s0 * D + c], b0 = zin[s0 * D + 32 + c];
            float a1 = zin[s1 * D + c], b1 = zin[s1 * D + 32 + c];
            np_ += a0 + a1; nn += b0 + b1;
        }
        if (j < n1) {
            int s0 = g_csrN[j];
            np_ += zin[s0 * D + c]; nn += zin[s0 * D + 32 + c];
        }
        float invP = 1.f / fmaxf((float)(p1 - p0), 1.f);
        float invN = 1.f / fmaxf((float)(n1 - n0), 1.f);
        st[c]       = pp * invP;  st[32 + c] = nn * invN;
        st[64 + c]  = pn * invP;  st[96 + c] = np_ * invN;
        st[128 + c] = zin[node * D + c];
        st[160 + c] = zin[node * D + 32 + c];
        __syncwarp();
        float accP = prb[c], accN = nrb[c];
#pragma unroll 8
        for (int k = 0; k < D; k++) {
            accP += st[k]      * s_pl[k * H2 + c];
            accN += st[64 + k] * s_nl[k * H2 + c];
        }
#pragma unroll 8
        for (int k = 0; k < H2; k++) {
            accP += st[128 + k] * s_prw[k * H2 + c];
            accN += st[160 + k] * s_nrw[k * H2 + c];
        }
        zout[node * D + c]      = fmaxf(accP, 0.f);
        zout[node * D + 32 + c] = fmaxf(accN, 0.f);
        __syncwarp();
    }
}

// ---------------- per-edge classifier (persistent) + |maskS| sum ----------------
__global__ void class_kernel(const int* __restrict__ e0, const int* __restrict__ e1,
                             const float* __restrict__ z,
                             const float* __restrict__ lw, const float* __restrict__ lb) {
    __shared__ float slw[2 * D * 3];
    __shared__ float slb[3];
    __shared__ float psum[8];
    for (int i = threadIdx.x; i < 2 * D * 3; i += 256) slw[i] = lw[i];
    if (threadIdx.x < 3) slb[threadIdx.x] = lb[threadIdx.x];
    __syncthreads();
    int w = threadIdx.x >> 5, lane = threadIdx.x & 31;
    float locsum = 0.f;
    for (int e = blockIdx.x * 8 + w; e < E; e += gridDim.x * 8) {
        int a = e0[e], b = e1[e];
        float za0 = z[a * D + lane], za1 = z[a * D + 32 + lane];
        float zb0 = z[b * D + lane], zb1 = z[b * D + 32 + lane];
        float v0 = za0 * slw[lane * 3 + 0] + za1 * slw[(32 + lane) * 3 + 0]
                 + zb0 * slw[(64 + lane) * 3 + 0] + zb1 * slw[(96 + lane) * 3 + 0];
        float v1 = za0 * slw[lane * 3 + 1] + za1 * slw[(32 + lane) * 3 + 1]
                 + zb0 * slw[(64 + lane) * 3 + 1] + zb1 * slw[(96 + lane) * 3 + 1];
        float v2 = za0 * slw[lane * 3 + 2] + za1 * slw[(32 + lane) * 3 + 2]
                 + zb0 * slw[(64 + lane) * 3 + 2] + zb1 * slw[(96 + lane) * 3 + 2];
#pragma unroll
        for (int off = 16; off; off >>= 1) {
            v0 += __shfl_xor_sync(0xffffffffu, v0, off);
            v1 += __shfl_xor_sync(0xffffffffu, v1, off);
            v2 += __shfl_xor_sync(0xffffffffu, v2, off);
        }
        if (lane == 0) {
            v0 += slb[0]; v1 += slb[1]; v2 += slb[2];
            int cls = 0; float best = v0;
            if (v1 > best) { best = v1; cls = 1; }
            if (v2 > best) { cls = 2; }
            float m = (float)(cls - 1);
            g_maskS[e] = m;
            locsum += fabsf(m);
        }
    }
    if (lane == 0) psum[w] = locsum;
    __syncthreads();
    if (threadIdx.x == 0) {
        float t = 0.f;
        for (int i = 0; i < 8; i++) t += psum[i];
        if (t != 0.f) atomicAdd(&g_sums[1], t);
    }
}

// ---------------- mask fusion path ----------------
__global__ void wedge_kernel(const int* __restrict__ e0, const float* __restrict__ fw) {
    int i = blockIdx.x * blockDim.x + threadIdx.x;
    if (i >= E) return;
    float w0 = fw[0], w1 = fw[1], w2 = fw[2];
    float m = fmaxf(w0, fmaxf(w1, w2));
    float ex0 = expf(w0 - m), ex1 = expf(w1 - m), ex2 = expf(w2 - m);
    float s = ex0 + ex1 + ex2;
    float sw0 = ex0 / s, sw1 = ex1 / s, sw2 = ex2 / s;
    float nO = 1.f / (float)E;
    float nF = g_maskF[i] / fmaxf(g_sums[0], 1e-12f);
    float nS = g_maskS[i] / fmaxf(g_sums[1], 1e-12f);
    float fused = sw0 * nO + sw1 * nF + sw2 * nS;
    float w = (fused > 0.5f) ? 1.f : 0.f;
    g_we[i] = w;
    if (w != 0.f) atomicAdd(&g_deg[e0[i]], w);
    unsigned msk = __ballot_sync(__activemask(), w != 0.f);
    if ((threadIdx.x & 31) == 0 && msk) atomicAdd(&g_nnz, __popc(msk));
}

// norm with inline rsqrt(deg) (dis_kernel folded in)
__global__ void norm_kernel(const int* __restrict__ e0, const int* __restrict__ e1) {
    int i = blockIdx.x * blockDim.x + threadIdx.x;
    if (i >= E) return;
    float w = g_we[i];
    if (w == 0.f) { g_norm[i] = 0.f; return; }
    float d0 = g_deg[e0[i]], d1 = g_deg[e1[i]];
    float r0 = (d0 > 0.f) ? rsqrtf(fmaxf(d0, 1e-12f)) : 0.f;
    float r1 = (d1 > 0.f) ? rsqrtf(fmaxf(d1, 1e-12f)) : 0.f;
    g_norm[i] = r0 * w * r1;
}

// ---------------- LightGCN ----------------
__global__ void initacc_out(const float* __restrict__ lgu, const float* __restrict__ lgi,
                            float* __restrict__ out) {
    int i = blockIdx.x * blockDim.x + threadIdx.x;
    if (i >= NN * D) return;
    constexpr int A = NU * D;
    float v;
    if (i < A) { v = lgu[i];     out[A + i]     = v; }
    else       { v = lgi[i - A]; out[2 * A + i] = v; }
    g_acc[i] = v;
    g_xk[i]  = v;
    g_xk2[i] = 0.f;
}

__device__ __forceinline__ void red_add_v4(float* p, float x, float y, float z, float w) {
    asm volatile("red.global.add.v4.f32 [%0], {%1,%2,%3,%4};"
                 :: "l"(p), "f"(x), "f"(y), "f"(z), "f"(w) : "memory");
}

// persistent, nnz-gated
__global__ void prop_kernel(const int* __restrict__ e0, const int* __restrict__ e1,
                            const float* __restrict__ xin, float* __restrict__ xout) {
    if (g_nnz == 0) return;
    for (long long t = (long long)blockIdx.x * blockDim.x + threadIdx.x;
         t < (long long)E * 16; t += (long long)gridDim.x * blockDim.x) {
        int e = (int)(t >> 4);
        float nm = g_norm[e];
        if (nm == 0.f) continue;
        int c = ((int)t & 15) * 4;
        int s = e1[e], d = e0[e];
        float4 v = *(const float4*)&xin[s * D + c];
        red_add_v4(&xout[d * D + c], nm * v.x, nm * v.y, nm * v.z, nm * v.w);
    }
}

__global__ void accadd_zero(const float* __restrict__ xnew, float* __restrict__ xold) {
    if (g_nnz == 0) return;
    for (int i = blockIdx.x * blockDim.x + threadIdx.x; i < NN * D;
         i += gridDim.x * blockDim.x) {
        g_acc[i] += xnew[i];
        xold[i] = 0.f;
    }
}

__global__ void out_final(const float* __restrict__ x3, float* __restrict__ out) {
    int i = blockIdx.x * blockDim.x + threadIdx.x;
    if (i >= NN * D) return;
    constexpr int A = NU * D;
    float v = (g_acc[i] + x3[i]) * 0.25f;
    if (i < A) out[i]     = v;
    else       out[A + i] = v;
}

// ---------------- launch ----------------
extern "C" void kernel_launch(void* const* d_in, const int* in_sizes, int n_in,
                              void* d_out, int out_size) {
    const float* user_feat = (const float*)d_in[0];
    const float* food_feat = (const float*)d_in[1];
    const int*   ei        = (const int*)d_in[2];
    const int*   pe        = (const int*)d_in[3];
    const int*   ne        = (const int*)d_in[4];
    const float* W_user    = (const float*)d_in[5];
    const float* b_user    = (const float*)d_in[6];
    const float* W_food    = (const float*)d_in[7];
    const float* b_food    = (const float*)d_in[8];
    const float* metric_w  = (const float*)d_in[9];
    const float* fusion_w  = (const float*)d_in[10];
    const float* sg_u      = (const float*)d_in[11];
    const float* sg_i      = (const float*)d_in[12];
    const float* c1_pl     = (const float*)d_in[13];
    const float* c1_prw    = (const float*)d_in[14];
    const float* c1_prb    = (const float*)d_in[15];
    const float* c1_nl     = (const float*)d_in[16];
    const float* c1_nrw    = (const float*)d_in[17];
    const float* c1_nrb    = (const float*)d_in[18];
    const float* cs_pl     = (const float*)d_in[19];
    const float* cs_prw    = (const float*)d_in[20];
    const float* cs_prb    = (const float*)d_in[21];
    const float* cs_nl     = (const float*)d_in[22];
    const float* cs_nrw    = (const float*)d_in[23];
    const float* cs_nrb    = (const float*)d_in[24];
    const float* lin_w     = (const float*)d_in[25];
    const float* lin_b     = (const float*)d_in[26];
    const float* lg_u      = (const float*)d_in[27];
    const float* lg_i      = (const float*)d_in[28];
    float* out = (float*)d_out;

    void *a_x, *a_y, *a_cnt2, *a_fill2, *a_deg, *a_sums, *a_nnz, *a_xk, *a_xk2;
    cudaGetSymbolAddress(&a_x, g_x);
    cudaGetSymbolAddress(&a_y, g_y);
    cudaGetSymbolAddress(&a_cnt2, g_cnt2);
    cudaGetSymbolAddress(&a_fill2, g_fill2);
    cudaGetSymbolAddress(&a_deg, g_deg);
    cudaGetSymbolAddress(&a_sums, g_sums);
    cudaGetSymbolAddress(&a_nnz, g_nnz);
    cudaGetSymbolAddress(&a_xk, g_xk);
    cudaGetSymbolAddress(&a_xk2, g_xk2);

    static cudaStream_t sB = 0, sC = 0;
    static cudaEvent_t evR = 0, evB = 0, evC = 0;
    static bool s_init = false;
    if (!s_init) {
        cudaStreamCreateWithFlags(&sB, cudaStreamNonBlocking);
        cudaStreamCreateWithFlags(&sC, cudaStreamNonBlocking);
        cudaEventCreateWithFlags(&evR, cudaEventDisableTiming);
        cudaEventCreateWithFlags(&evB, cudaEventDisableTiming);
        cudaEventCreateWithFlags(&evC, cudaEventDisableTiming);
        s_init = true;
    }

    const int TPB = 256;
    const int gE     = (E + TPB - 1) / TPB;
    const int gBE    = (EP + EN + TPB - 1) / TPB;
    const int gND    = (NN * D + TPB - 1) / TPB;
    const int nScanBlocks = (2 * NN + 1023) / 1024;
    constexpr int NBU = (NU + 127) / 128;

    // zero the cross-chain accumulators BEFORE the fork so sim/class sums are ordered
    cudaMemsetAsync(a_sums, 0, 2 * sizeof(float));
    cudaMemsetAsync(a_nnz, 0, sizeof(int));
    cudaMemsetAsync(a_deg, 0, NN * sizeof(float));

    // fork
    cudaEventRecord(evR, 0);
    if (sB) cudaStreamWaitEvent(sB, evR, 0);
    if (sC) cudaStreamWaitEvent(sC, evR, 0);

    // ---- chain B (sB): CSR -> conv x3 -> class(+|maskS| sum) ----
    cudaMemsetAsync(a_cnt2, 0, 2 * NN * sizeof(int), sB);
    cudaMemsetAsync(a_fill2, 0, 2 * NN * sizeof(int), sB);
    hist_kernel<<<gBE, TPB, 0, sB>>>(pe + EP, ne + EN);
    scan1_kernel<<<nScanBlocks, 1024, 0, sB>>>();
    scan2_kernel<<<1, 256, 0, sB>>>(nScanBlocks);
    scan3_kernel<<<(2 * NN + TPB - 1) / TPB, TPB, 0, sB>>>();
    fill_csr<<<gBE, TPB, 0, sB>>>(pe, ne);
    conv1_fused<<<PG_CONV, TPB, 0, sB>>>(sg_u, sg_i,
                                         c1_pl, c1_prw, c1_prb, c1_nl, c1_nrw, c1_nrb);
    conv2_fused<<<PG_CONV, TPB, 0, sB>>>(cs_pl, cs_prw, cs_prb, cs_nl, cs_nrw, cs_nrb,
                                         (const float*)a_y, (float*)a_x);
    conv2_fused<<<PG_CONV, TPB, 0, sB>>>(cs_pl + D * H2, cs_prw + H2 * H2, cs_prb + H2,
                                         cs_nl + D * H2, cs_nrw + H2 * H2, cs_nrb + H2,
                                         (const float*)a_x, (float*)a_y);
    class_kernel<<<PG_EDGE, TPB, 0, sB>>>(ei, ei + E, (const float*)a_y, lin_w, lin_b);
    cudaEventRecord(evB, sB);

    // ---- chain C (sC): LightGCN init + lg output copies ----
    initacc_out<<<gND, TPB, 0, sC>>>(lg_u, lg_i, out);
    cudaEventRecord(evC, sC);

    // ---- chain A (origin): GEMMs -> norms -> sim(+|maskF| sum) ----
    gemm2<<<2 * NBU, 256>>>(user_feat, W_user, b_user, food_feat, W_food, b_food);
    node_norms2<<<PG_NRM, TPB>>>(metric_w);
    sim_kernel<<<PG_EDGE, TPB>>>(ei, ei + E, metric_w);

    // join
    cudaStreamWaitEvent(0, evB, 0);
    cudaStreamWaitEvent(0, evC, 0);

    // ---- tail ----
    wedge_kernel<<<gE, TPB>>>(ei, fusion_w);
    norm_kernel<<<gE, TPB>>>(ei, ei + E);

    prop_kernel<<<PG_TAIL, TPB>>>(ei, ei + E, (const float*)a_xk, (float*)a_xk2);
    accadd_zero<<<PG_TAIL, TPB>>>((const float*)a_xk2, (float*)a_xk);
    prop_kernel<<<PG_TAIL, TPB>>>(ei, ei + E, (const float*)a_xk2, (float*)a_xk);
    accadd_zero<<<PG_TAIL, TPB>>>((const float*)a_xk, (float*)a_xk2);
    prop_kernel<<<PG_TAIL, TPB>>>(ei, ei + E, (const float*)a_xk, (float*)a_xk2);
    out_final<<<gND, TPB>>>((const float*)a_xk2, out);
}